// round 3
// baseline (speedup 1.0000x reference)
#include <cuda_runtime.h>
#include <math.h>

#define N_PTS 131072
#define C 128
#define KNUM 27
#define M_MAP 65536
#define EPS 1e-5f

#define BM 64
#define BK 32

// ---- scratch (static device allocations; allowed) ----
__device__ __align__(16) float g_acc[(size_t)N_PTS * C];   // 64 MB accumulator
__device__ __align__(16) float g_y[(size_t)N_PTS * C];     // 64 MB intermediate
__device__ __align__(16) float g_sum[C];
__device__ __align__(16) float g_sq[C];
__device__ __align__(16) float g_scale[C];
__device__ __align__(16) float g_shift[C];

// ---------------------------------------------------------------------------
// Sparse conv: per (block tile of 64 map rows, kernel offset k):
//   contrib[64,128] = x[map_in[k, m0:m0+64]] @ W[k]   (C=128 reduce)
//   atomicAdd into acc[map_out[k, m]][:]
// ---------------------------------------------------------------------------
__global__ __launch_bounds__(256, 4)
void spconv_kernel(const float* __restrict__ x,
                   const float* __restrict__ W,
                   const int* __restrict__ map_in,
                   const int* __restrict__ map_out,
                   float* __restrict__ acc)
{
    __shared__ float As[BK][BM + 1];   // transposed A tile, padded (conflict-free)
    __shared__ float Bs[BK][C];        // B tile

    const int k   = blockIdx.y;
    const int m0  = blockIdx.x * BM;
    const int tid = threadIdx.x;
    const int tx  = tid & 15;          // column group: cols tx*4..+3 and tx*4+64..+67
    const int ty  = tid >> 4;          // row group: rows ty*4..+3

    const int*   mi = map_in  + (size_t)k * M_MAP + m0;
    const int*   mo = map_out + (size_t)k * M_MAP + m0;
    const float* Wk = W + (size_t)k * C * C;

    // gather row indices for the two A-tile loads this thread performs
    const int rowA0 = tid >> 3;            // 0..31
    const int rowA1 = (tid + 256) >> 3;    // 32..63
    const int c4    = tid & 7;             // which float4 within the 32-col slab
    const int gr0 = mi[rowA0];
    const int gr1 = mi[rowA1];

    float accr[4][8];
    #pragma unroll
    for (int i = 0; i < 4; i++)
        #pragma unroll
        for (int j = 0; j < 8; j++) accr[i][j] = 0.0f;

    for (int kk0 = 0; kk0 < C; kk0 += BK) {
        // ---- load A (gathered), store transposed ----
        {
            float4 v0 = *(const float4*)(x + (size_t)gr0 * C + kk0 + c4 * 4);
            float4 v1 = *(const float4*)(x + (size_t)gr1 * C + kk0 + c4 * 4);
            As[c4 * 4 + 0][rowA0] = v0.x;
            As[c4 * 4 + 1][rowA0] = v0.y;
            As[c4 * 4 + 2][rowA0] = v0.z;
            As[c4 * 4 + 3][rowA0] = v0.w;
            As[c4 * 4 + 0][rowA1] = v1.x;
            As[c4 * 4 + 1][rowA1] = v1.y;
            As[c4 * 4 + 2][rowA1] = v1.z;
            As[c4 * 4 + 3][rowA1] = v1.w;
        }
        // ---- load B: rows kk0..kk0+31, all 128 cols (contiguous) ----
        #pragma unroll
        for (int i = 0; i < 4; i++) {
            int l   = tid + i * 256;
            int row = l >> 5;          // 0..31
            int cc  = l & 31;          // float4 index in row
            *(float4*)&Bs[row][cc * 4] =
                *(const float4*)(Wk + (size_t)(kk0 + row) * C + cc * 4);
        }
        __syncthreads();

        // ---- FMA microkernel ----
        #pragma unroll
        for (int kk = 0; kk < BK; kk++) {
            float a0 = As[kk][ty * 4 + 0];
            float a1 = As[kk][ty * 4 + 1];
            float a2 = As[kk][ty * 4 + 2];
            float a3 = As[kk][ty * 4 + 3];
            float4 b0 = *(const float4*)&Bs[kk][tx * 4];
            float4 b1 = *(const float4*)&Bs[kk][tx * 4 + 64];
            float bb[8] = {b0.x, b0.y, b0.z, b0.w, b1.x, b1.y, b1.z, b1.w};
            #pragma unroll
            for (int j = 0; j < 8; j++) {
                accr[0][j] = fmaf(a0, bb[j], accr[0][j]);
                accr[1][j] = fmaf(a1, bb[j], accr[1][j]);
                accr[2][j] = fmaf(a2, bb[j], accr[2][j]);
                accr[3][j] = fmaf(a3, bb[j], accr[3][j]);
            }
        }
        __syncthreads();
    }

    // ---- scatter-add ----
    #pragma unroll
    for (int i = 0; i < 4; i++) {
        int ro = mo[ty * 4 + i];
        float* dst = acc + (size_t)ro * C;
        #pragma unroll
        for (int j = 0; j < 4; j++) {
            atomicAdd(dst + tx * 4 + j,      accr[i][j]);
            atomicAdd(dst + tx * 4 + 64 + j, accr[i][j + 4]);
        }
    }
}

// ---------------------------------------------------------------------------
// BN stats: per-channel sum & sum-of-squares over N rows.
// ---------------------------------------------------------------------------
__global__ void zero_stats_kernel()
{
    int c = threadIdx.x;
    g_sum[c] = 0.0f;
    g_sq[c]  = 0.0f;
}

__global__ __launch_bounds__(256)
void bn_stats_kernel(const float* __restrict__ a)
{
    __shared__ float ss[256];
    __shared__ float sq[256];
    const int tid = threadIdx.x;
    const int c   = tid & 127;
    const int sub = tid >> 7;   // 0/1

    float s = 0.0f, q = 0.0f;
    for (int r = blockIdx.x * 2 + sub; r < N_PTS; r += gridDim.x * 2) {
        float v = a[(size_t)r * C + c];
        s += v;
        q += v * v;
    }
    ss[tid] = s;
    sq[tid] = q;
    __syncthreads();
    if (tid < 128) {
        atomicAdd(&g_sum[c], ss[tid] + ss[tid + 128]);
        atomicAdd(&g_sq[c],  sq[tid] + sq[tid + 128]);
    }
}

__global__ void bn_finalize_kernel(const float* __restrict__ gamma,
                                   const float* __restrict__ beta)
{
    int c = threadIdx.x;
    float m  = g_sum[c] * (1.0f / N_PTS);
    float v  = g_sq[c] * (1.0f / N_PTS) - m * m;
    float is = rsqrtf(v + EPS);
    float sc = is * gamma[c];
    g_scale[c] = sc;
    g_shift[c] = beta[c] - m * sc;
}

// ---------------------------------------------------------------------------
// Apply kernels (vectorized float4)
// ---------------------------------------------------------------------------
__device__ __forceinline__ float elu_f(float x)
{
    return x > 0.0f ? x : expm1f(x);
}

__global__ __launch_bounds__(256)
void apply_bn_elu_kernel(const float* __restrict__ a, float* __restrict__ o)
{
    int idx = blockIdx.x * blockDim.x + threadIdx.x;   // float4 index
    int c4  = idx & 31;                                // 32 float4 per row
    float4 v  = ((const float4*)a)[idx];
    float4 sc = ((const float4*)g_scale)[c4];
    float4 sh = ((const float4*)g_shift)[c4];
    float4 r;
    r.x = elu_f(fmaf(v.x, sc.x, sh.x));
    r.y = elu_f(fmaf(v.y, sc.y, sh.y));
    r.z = elu_f(fmaf(v.z, sc.z, sh.z));
    r.w = elu_f(fmaf(v.w, sc.w, sh.w));
    ((float4*)o)[idx] = r;
}

__global__ __launch_bounds__(256)
void apply_bn_res_elu_kernel(const float* __restrict__ a,
                             const float* __restrict__ resid,
                             float* __restrict__ o)
{
    int idx = blockIdx.x * blockDim.x + threadIdx.x;
    int c4  = idx & 31;
    float4 v  = ((const float4*)a)[idx];
    float4 rs = ((const float4*)resid)[idx];
    float4 sc = ((const float4*)g_scale)[c4];
    float4 sh = ((const float4*)g_shift)[c4];
    float4 r;
    r.x = elu_f(fmaf(v.x, sc.x, sh.x) + rs.x);
    r.y = elu_f(fmaf(v.y, sc.y, sh.y) + rs.y);
    r.z = elu_f(fmaf(v.z, sc.z, sh.z) + rs.z);
    r.w = elu_f(fmaf(v.w, sc.w, sh.w) + rs.w);
    ((float4*)o)[idx] = r;
}

// ---------------------------------------------------------------------------
// Launch
// ---------------------------------------------------------------------------
extern "C" void kernel_launch(void* const* d_in, const int* in_sizes, int n_in,
                              void* d_out, int out_size)
{
    const float* x       = (const float*)d_in[0];
    const float* W1      = (const float*)d_in[1];
    const float* gamma1  = (const float*)d_in[2];
    const float* beta1   = (const float*)d_in[3];
    const float* W2      = (const float*)d_in[4];
    const float* gamma2  = (const float*)d_in[5];
    const float* beta2   = (const float*)d_in[6];
    const int*   map1_in  = (const int*)d_in[7];
    const int*   map1_out = (const int*)d_in[8];
    const int*   map2_in  = (const int*)d_in[9];
    const int*   map2_out = (const int*)d_in[10];
    float* out = (float*)d_out;

    void* accPtr = nullptr;
    void* yPtr   = nullptr;
    cudaGetSymbolAddress(&accPtr, g_acc);
    cudaGetSymbolAddress(&yPtr, g_y);
    const size_t accBytes = (size_t)N_PTS * C * sizeof(float);

    const dim3 convGrid(M_MAP / BM, KNUM);
    const int  elem4   = (N_PTS * C) / 4;
    const int  ewGrid  = elem4 / 256;

    // ---- layer 1 ----
    cudaMemsetAsync(accPtr, 0, accBytes);
    zero_stats_kernel<<<1, C>>>();
    spconv_kernel<<<convGrid, 256>>>(x, W1, map1_in, map1_out, (float*)accPtr);
    bn_stats_kernel<<<256, 256>>>((const float*)accPtr);
    bn_finalize_kernel<<<1, C>>>(gamma1, beta1);
    apply_bn_elu_kernel<<<ewGrid, 256>>>((const float*)accPtr, (float*)yPtr);

    // ---- layer 2 ----
    cudaMemsetAsync(accPtr, 0, accBytes);
    zero_stats_kernel<<<1, C>>>();
    spconv_kernel<<<convGrid, 256>>>((const float*)yPtr, W2, map2_in, map2_out,
                                     (float*)accPtr);
    bn_stats_kernel<<<256, 256>>>((const float*)accPtr);
    bn_finalize_kernel<<<1, C>>>(gamma2, beta2);
    apply_bn_res_elu_kernel<<<ewGrid, 256>>>((const float*)accPtr, x, out);
}

// round 4
// speedup vs baseline: 1.7103x; 1.7103x over previous
#include <cuda_runtime.h>
#include <cuda_bf16.h>
#include <math.h>

#define N_PTS 131072
#define C 128
#define KNUM 27
#define M_MAP 65536
#define EPS 1e-5f

#define BT 128          // block tile rows (map entries)
#define KC 32           // K chunk
#define AP 40           // smem pitch in bf16 elems (conflict-free for frag loads)
#define CP 132          // output stage pitch in floats

// ---- scratch (static device allocations; allowed) ----
__device__ __align__(16) float         g_acc[(size_t)N_PTS * C];     // 64 MB
__device__ __align__(16) __nv_bfloat16 g_xhi[(size_t)N_PTS * C];     // 32 MB
__device__ __align__(16) __nv_bfloat16 g_xlo[(size_t)N_PTS * C];     // 32 MB
__device__ __align__(16) __nv_bfloat16 g_yhi[(size_t)N_PTS * C];     // 32 MB
__device__ __align__(16) __nv_bfloat16 g_ylo[(size_t)N_PTS * C];     // 32 MB
__device__ __align__(16) __nv_bfloat16 g_wthi[(size_t)KNUM * C * C]; // W^T hi: [k][n][cin]
__device__ __align__(16) __nv_bfloat16 g_wtlo[(size_t)KNUM * C * C];
__device__ __align__(16) float g_sum[C];
__device__ __align__(16) float g_sq[C];
__device__ __align__(16) float g_scale[C];
__device__ __align__(16) float g_shift[C];

// ---------------------------------------------------------------------------
// Prepack: split fp32 -> (bf16 hi, bf16 lo)
// ---------------------------------------------------------------------------
__device__ __forceinline__ void split_bf16(float v, __nv_bfloat16& h, __nv_bfloat16& l)
{
    h = __float2bfloat16_rn(v);
    l = __float2bfloat16_rn(v - __bfloat162float(h));
}

__global__ __launch_bounds__(256)
void prepack_x_kernel(const float* __restrict__ src,
                      __nv_bfloat16* __restrict__ hi,
                      __nv_bfloat16* __restrict__ lo)
{
    size_t i = (size_t)blockIdx.x * 256 + threadIdx.x;   // float4 index
    float4 v = ((const float4*)src)[i];
    __nv_bfloat16 h0, h1, h2, h3, l0, l1, l2, l3;
    split_bf16(v.x, h0, l0); split_bf16(v.y, h1, l1);
    split_bf16(v.z, h2, l2); split_bf16(v.w, h3, l3);
    ((__nv_bfloat162*)hi)[i * 2 + 0] = __nv_bfloat162(h0, h1);
    ((__nv_bfloat162*)hi)[i * 2 + 1] = __nv_bfloat162(h2, h3);
    ((__nv_bfloat162*)lo)[i * 2 + 0] = __nv_bfloat162(l0, l1);
    ((__nv_bfloat162*)lo)[i * 2 + 1] = __nv_bfloat162(l2, l3);
}

// W[k][cin][n] fp32 -> W^T[k][n][cin] split bf16
__global__ __launch_bounds__(256)
void prepack_w_kernel(const float* __restrict__ W)
{
    int k = blockIdx.x;
    const float* Wk = W + (size_t)k * C * C;
    __nv_bfloat16* oh = g_wthi + (size_t)k * C * C;
    __nv_bfloat16* ol = g_wtlo + (size_t)k * C * C;
    for (int idx = threadIdx.x; idx < C * C; idx += 256) {
        int n = idx & (C - 1);
        int cin = idx >> 7;
        float v = Wk[(size_t)cin * C + n];
        __nv_bfloat16 h, l;
        split_bf16(v, h, l);
        oh[(size_t)n * C + cin] = h;
        ol[(size_t)n * C + cin] = l;
    }
}

// ---------------------------------------------------------------------------
// MMA helper: m16n8k16 bf16, fp32 accumulate
// ---------------------------------------------------------------------------
__device__ __forceinline__ void mma16816(float* c, const unsigned* a,
                                         unsigned b0, unsigned b1)
{
    asm volatile(
        "mma.sync.aligned.m16n8k16.row.col.f32.bf16.bf16.f32 "
        "{%0,%1,%2,%3}, {%4,%5,%6,%7}, {%8,%9}, {%0,%1,%2,%3};"
        : "+f"(c[0]), "+f"(c[1]), "+f"(c[2]), "+f"(c[3])
        : "r"(a[0]), "r"(a[1]), "r"(a[2]), "r"(a[3]), "r"(b0), "r"(b1));
}

// ---------------------------------------------------------------------------
// Sparse conv via tensor cores:
// block = (128 map rows, all 128 out channels), K=128 reduce, 3-mma bf16 split.
// Output staged in SMEM, scattered with red.global.v4.f32.add.
// ---------------------------------------------------------------------------
__global__ __launch_bounds__(256, 2)
void spconv_mma_kernel(const __nv_bfloat16* __restrict__ xhi,
                       const __nv_bfloat16* __restrict__ xlo,
                       const int* __restrict__ map_in,
                       const int* __restrict__ map_out,
                       float* __restrict__ acc_out)
{
    extern __shared__ char dynsmem[];
    __nv_bfloat16* As_hi = (__nv_bfloat16*)dynsmem;                 // [128][AP]
    __nv_bfloat16* As_lo = As_hi + BT * AP;
    __nv_bfloat16* Bs_hi = As_lo + BT * AP;                         // [n][AP]
    __nv_bfloat16* Bs_lo = Bs_hi + BT * AP;
    float*         Cs    = (float*)dynsmem;                         // [128][CP] (reused)
    __shared__ int rowidx[BT];

    const int k   = blockIdx.y;
    const int m0  = blockIdx.x * BT;
    const int tid = threadIdx.x;
    const int warp = tid >> 5;
    const int lane = tid & 31;
    const int wm = warp & 3;        // 4 warps along M (32 rows each)
    const int wn = warp >> 2;       // 2 warps along N (64 cols each)
    const int g   = lane >> 2;      // 0..7
    const int tig = lane & 3;       // 0..3

    const int* mi = map_in  + (size_t)k * M_MAP + m0;
    const int* mo = map_out + (size_t)k * M_MAP + m0;
    const __nv_bfloat16* wh = g_wthi + (size_t)k * C * C;
    const __nv_bfloat16* wl = g_wtlo + (size_t)k * C * C;

    if (tid < BT) rowidx[tid] = mi[tid];
    __syncthreads();

    float accr[2][8][4];
    #pragma unroll
    for (int i = 0; i < 2; i++)
        #pragma unroll
        for (int j = 0; j < 8; j++)
            #pragma unroll
            for (int q = 0; q < 4; q++) accr[i][j][q] = 0.0f;

    for (int ch = 0; ch < C / KC; ch++) {
        const int kk0 = ch * KC;
        // ---- fill A (gathered) and B (weights) chunks: 8 bf16 (16B) per transfer ----
        #pragma unroll
        for (int it = 0; it < 2; it++) {
            int idx = tid + it * 256;          // 0..511
            int row = idx >> 2;                // 0..127
            int q   = idx & 3;                 // 16B slab within 32 k-elems
            size_t srcA = (size_t)rowidx[row] * C + kk0 + q * 8;
            size_t srcB = (size_t)row * C + kk0 + q * 8;
            *(uint4*)(As_hi + row * AP + q * 8) = *(const uint4*)(xhi + srcA);
            *(uint4*)(As_lo + row * AP + q * 8) = *(const uint4*)(xlo + srcA);
            *(uint4*)(Bs_hi + row * AP + q * 8) = *(const uint4*)(wh + srcB);
            *(uint4*)(Bs_lo + row * AP + q * 8) = *(const uint4*)(wl + srcB);
        }
        __syncthreads();

        #pragma unroll
        for (int ks = 0; ks < 2; ks++) {
            const int kb = ks * 16;
            const int kcol = kb + tig * 2;
            unsigned ah[2][4], al[2][4];
            #pragma unroll
            for (int mi2 = 0; mi2 < 2; mi2++) {
                int r0 = wm * 32 + mi2 * 16 + g;
                ah[mi2][0] = *(const unsigned*)(As_hi + r0 * AP + kcol);
                ah[mi2][1] = *(const unsigned*)(As_hi + (r0 + 8) * AP + kcol);
                ah[mi2][2] = *(const unsigned*)(As_hi + r0 * AP + kcol + 8);
                ah[mi2][3] = *(const unsigned*)(As_hi + (r0 + 8) * AP + kcol + 8);
                al[mi2][0] = *(const unsigned*)(As_lo + r0 * AP + kcol);
                al[mi2][1] = *(const unsigned*)(As_lo + (r0 + 8) * AP + kcol);
                al[mi2][2] = *(const unsigned*)(As_lo + r0 * AP + kcol + 8);
                al[mi2][3] = *(const unsigned*)(As_lo + (r0 + 8) * AP + kcol + 8);
            }
            #pragma unroll
            for (int ni = 0; ni < 8; ni++) {
                int n = wn * 64 + ni * 8 + g;
                unsigned bh0 = *(const unsigned*)(Bs_hi + n * AP + kcol);
                unsigned bh1 = *(const unsigned*)(Bs_hi + n * AP + kcol + 8);
                unsigned bl0 = *(const unsigned*)(Bs_lo + n * AP + kcol);
                unsigned bl1 = *(const unsigned*)(Bs_lo + n * AP + kcol + 8);
                #pragma unroll
                for (int mi2 = 0; mi2 < 2; mi2++) {
                    mma16816(accr[mi2][ni], ah[mi2], bh0, bh1);
                    mma16816(accr[mi2][ni], ah[mi2], bl0, bl1);
                    mma16816(accr[mi2][ni], al[mi2], bh0, bh1);
                }
            }
        }
        __syncthreads();
    }

    // ---- stage output tile in SMEM (fp32) ----
    #pragma unroll
    for (int mi2 = 0; mi2 < 2; mi2++) {
        #pragma unroll
        for (int ni = 0; ni < 8; ni++) {
            int r0 = wm * 32 + mi2 * 16 + g;
            int cc = wn * 64 + ni * 8 + tig * 2;
            *(float2*)&Cs[r0 * CP + cc]       = make_float2(accr[mi2][ni][0], accr[mi2][ni][1]);
            *(float2*)&Cs[(r0 + 8) * CP + cc] = make_float2(accr[mi2][ni][2], accr[mi2][ni][3]);
        }
    }
    __syncthreads();

    // ---- scatter with 16B vector reductions: 2 threads per row, 64 cols each ----
    {
        int r = tid >> 1;
        int half = tid & 1;
        int orow = mo[r];
        float* dst = acc_out + (size_t)orow * C + half * 64;
        const float* src = &Cs[r * CP + half * 64];
        #pragma unroll
        for (int j = 0; j < 16; j++) {
            float4 v = *(const float4*)(src + j * 4);
            asm volatile("red.global.v4.f32.add [%0], {%1, %2, %3, %4};"
                         :: "l"(dst + j * 4), "f"(v.x), "f"(v.y), "f"(v.z), "f"(v.w)
                         : "memory");
        }
    }
}

// ---------------------------------------------------------------------------
// BN stats / finalize
// ---------------------------------------------------------------------------
__global__ void zero_stats_kernel()
{
    int c = threadIdx.x;
    g_sum[c] = 0.0f;
    g_sq[c]  = 0.0f;
}

__global__ __launch_bounds__(256)
void bn_stats_kernel(const float* __restrict__ a)
{
    __shared__ float ss[256];
    __shared__ float sq[256];
    const int tid = threadIdx.x;
    const int c   = tid & 127;
    const int sub = tid >> 7;

    float s = 0.0f, q = 0.0f;
    for (int r = blockIdx.x * 2 + sub; r < N_PTS; r += gridDim.x * 2) {
        float v = a[(size_t)r * C + c];
        s += v;
        q += v * v;
    }
    ss[tid] = s;
    sq[tid] = q;
    __syncthreads();
    if (tid < 128) {
        atomicAdd(&g_sum[c], ss[tid] + ss[tid + 128]);
        atomicAdd(&g_sq[c],  sq[tid] + sq[tid + 128]);
    }
}

__global__ void bn_finalize_kernel(const float* __restrict__ gamma,
                                   const float* __restrict__ beta)
{
    int c = threadIdx.x;
    float m  = g_sum[c] * (1.0f / N_PTS);
    float v  = g_sq[c] * (1.0f / N_PTS) - m * m;
    float is = rsqrtf(v + EPS);
    float sc = is * gamma[c];
    g_scale[c] = sc;
    g_shift[c] = beta[c] - m * sc;
}

// ---------------------------------------------------------------------------
// Apply kernels
// ---------------------------------------------------------------------------
__device__ __forceinline__ float elu_f(float x)
{
    return x > 0.0f ? x : expm1f(x);
}

// BN + ELU, write split bf16 (input to layer-2 conv)
__global__ __launch_bounds__(256)
void apply_bn_elu_split_kernel(const float* __restrict__ a,
                               __nv_bfloat16* __restrict__ yh,
                               __nv_bfloat16* __restrict__ yl)
{
    size_t idx = (size_t)blockIdx.x * 256 + threadIdx.x;
    int c4 = (int)(idx & 31);
    float4 v  = ((const float4*)a)[idx];
    float4 sc = ((const float4*)g_scale)[c4];
    float4 sh = ((const float4*)g_shift)[c4];
    float4 r;
    r.x = elu_f(fmaf(v.x, sc.x, sh.x));
    r.y = elu_f(fmaf(v.y, sc.y, sh.y));
    r.z = elu_f(fmaf(v.z, sc.z, sh.z));
    r.w = elu_f(fmaf(v.w, sc.w, sh.w));
    __nv_bfloat16 h0, h1, h2, h3, l0, l1, l2, l3;
    split_bf16(r.x, h0, l0); split_bf16(r.y, h1, l1);
    split_bf16(r.z, h2, l2); split_bf16(r.w, h3, l3);
    ((__nv_bfloat162*)yh)[idx * 2 + 0] = __nv_bfloat162(h0, h1);
    ((__nv_bfloat162*)yh)[idx * 2 + 1] = __nv_bfloat162(h2, h3);
    ((__nv_bfloat162*)yl)[idx * 2 + 0] = __nv_bfloat162(l0, l1);
    ((__nv_bfloat162*)yl)[idx * 2 + 1] = __nv_bfloat162(l2, l3);
}

// BN + residual + ELU -> final output
__global__ __launch_bounds__(256)
void apply_bn_res_elu_kernel(const float* __restrict__ a,
                             const float* __restrict__ resid,
                             float* __restrict__ o)
{
    size_t idx = (size_t)blockIdx.x * 256 + threadIdx.x;
    int c4 = (int)(idx & 31);
    float4 v  = ((const float4*)a)[idx];
    float4 rs = ((const float4*)resid)[idx];
    float4 sc = ((const float4*)g_scale)[c4];
    float4 sh = ((const float4*)g_shift)[c4];
    float4 r;
    r.x = elu_f(fmaf(v.x, sc.x, sh.x) + rs.x);
    r.y = elu_f(fmaf(v.y, sc.y, sh.y) + rs.y);
    r.z = elu_f(fmaf(v.z, sc.z, sh.z) + rs.z);
    r.w = elu_f(fmaf(v.w, sc.w, sh.w) + rs.w);
    ((float4*)o)[idx] = r;
}

// ---------------------------------------------------------------------------
// Launch
// ---------------------------------------------------------------------------
extern "C" void kernel_launch(void* const* d_in, const int* in_sizes, int n_in,
                              void* d_out, int out_size)
{
    const float* x       = (const float*)d_in[0];
    const float* W1      = (const float*)d_in[1];
    const float* gamma1  = (const float*)d_in[2];
    const float* beta1   = (const float*)d_in[3];
    const float* W2      = (const float*)d_in[4];
    const float* gamma2  = (const float*)d_in[5];
    const float* beta2   = (const float*)d_in[6];
    const int*   map1_in  = (const int*)d_in[7];
    const int*   map1_out = (const int*)d_in[8];
    const int*   map2_in  = (const int*)d_in[9];
    const int*   map2_out = (const int*)d_in[10];
    float* out = (float*)d_out;

    void *accPtr, *xhiPtr, *xloPtr, *yhiPtr, *yloPtr;
    cudaGetSymbolAddress(&accPtr, g_acc);
    cudaGetSymbolAddress(&xhiPtr, g_xhi);
    cudaGetSymbolAddress(&xloPtr, g_xlo);
    cudaGetSymbolAddress(&yhiPtr, g_yhi);
    cudaGetSymbolAddress(&yloPtr, g_ylo);
    const size_t accBytes = (size_t)N_PTS * C * sizeof(float);

    const int DYN_SMEM = BT * CP * sizeof(float);   // 67584 (>= chunk area 40960)
    cudaFuncSetAttribute(spconv_mma_kernel,
                         cudaFuncAttributeMaxDynamicSharedMemorySize, DYN_SMEM);

    const dim3 convGrid(M_MAP / BT, KNUM);
    const int  elem4  = (N_PTS * C) / 4;
    const int  ewGrid = elem4 / 256;

    // ---- prepack ----
    prepack_x_kernel<<<ewGrid, 256>>>(x, (__nv_bfloat16*)xhiPtr, (__nv_bfloat16*)xloPtr);
    prepack_w_kernel<<<KNUM, 256>>>(W1);   // -> g_wthi/g_wtlo [0..KNUM)
    cudaMemsetAsync(accPtr, 0, accBytes);
    zero_stats_kernel<<<1, C>>>();

    // ---- layer 1 ----
    spconv_mma_kernel<<<convGrid, 256, DYN_SMEM>>>(
        (const __nv_bfloat16*)xhiPtr, (const __nv_bfloat16*)xloPtr,
        map1_in, map1_out, (float*)accPtr);
    bn_stats_kernel<<<256, 256>>>((const float*)accPtr);
    bn_finalize_kernel<<<1, C>>>(gamma1, beta1);
    apply_bn_elu_split_kernel<<<ewGrid, 256>>>(
        (const float*)accPtr, (__nv_bfloat16*)yhiPtr, (__nv_bfloat16*)yloPtr);

    // ---- layer 2 ----
    prepack_w_kernel<<<KNUM, 256>>>(W2);
    cudaMemsetAsync(accPtr, 0, accBytes);
    zero_stats_kernel<<<1, C>>>();
    spconv_mma_kernel<<<convGrid, 256, DYN_SMEM>>>(
        (const __nv_bfloat16*)yhiPtr, (const __nv_bfloat16*)yloPtr,
        map2_in, map2_out, (float*)accPtr);
    bn_stats_kernel<<<256, 256>>>((const float*)accPtr);
    bn_finalize_kernel<<<1, C>>>(gamma2, beta2);
    apply_bn_res_elu_kernel<<<ewGrid, 256>>>((const float*)accPtr, x, out);
}

// round 6
// speedup vs baseline: 2.0009x; 1.1699x over previous
#include <cuda_runtime.h>
#include <cuda_bf16.h>
#include <math.h>
#include <stdint.h>

#define N_PTS 131072
#define C 128
#define KNUM 27
#define M_MAP 65536
#define EPS 1e-5f

#define BT 128            // map rows per CTA tile
#define KC 32             // k-elems per chunk
#define NCHUNK (C / KC)   // 4
#define PB 80             // smem row pitch in BYTES (40 bf16) — LDSM conflict-free
#define ARR_SZ (BT * PB)  // 10240 B per operand array
#define STAGE_SZ (4 * ARR_SZ)   // Ahi, Alo, Bhi, Blo = 40960 B
#define DYN_SMEM (2 * STAGE_SZ) // 81920 B (2 stages); Cs (67584 B) aliases this
#define CP 132            // output stage pitch in floats

// ---- scratch (static device allocations; allowed) ----
__device__ __align__(16) float         g_acc[(size_t)N_PTS * C];
__device__ __align__(16) __nv_bfloat16 g_xhi[(size_t)N_PTS * C];
__device__ __align__(16) __nv_bfloat16 g_xlo[(size_t)N_PTS * C];
__device__ __align__(16) __nv_bfloat16 g_yhi[(size_t)N_PTS * C];
__device__ __align__(16) __nv_bfloat16 g_ylo[(size_t)N_PTS * C];
__device__ __align__(16) __nv_bfloat16 g_wthi[(size_t)KNUM * C * C]; // W^T: [k][n][cin]
__device__ __align__(16) __nv_bfloat16 g_wtlo[(size_t)KNUM * C * C];
__device__ __align__(16) float g_sum[C];
__device__ __align__(16) float g_sq[C];
__device__ __align__(16) float g_scale[C];
__device__ __align__(16) float g_shift[C];

// ---------------------------------------------------------------------------
// helpers
// ---------------------------------------------------------------------------
__device__ __forceinline__ uint32_t smem_u32(const void* p)
{
    uint32_t a;
    asm("{ .reg .u64 t; cvta.to.shared.u64 t, %1; cvt.u32.u64 %0, t; }"
        : "=r"(a) : "l"(p));
    return a;
}

__device__ __forceinline__ void split_bf16(float v, __nv_bfloat16& h, __nv_bfloat16& l)
{
    h = __float2bfloat16_rn(v);
    l = __float2bfloat16_rn(v - __bfloat162float(h));
}

__device__ __forceinline__ void mma16816(float* c, const unsigned* a,
                                         unsigned b0, unsigned b1)
{
    asm volatile(
        "mma.sync.aligned.m16n8k16.row.col.f32.bf16.bf16.f32 "
        "{%0,%1,%2,%3}, {%4,%5,%6,%7}, {%8,%9}, {%0,%1,%2,%3};"
        : "+f"(c[0]), "+f"(c[1]), "+f"(c[2]), "+f"(c[3])
        : "r"(a[0]), "r"(a[1]), "r"(a[2]), "r"(a[3]), "r"(b0), "r"(b1));
}

__device__ __forceinline__ void ldsm_x4(unsigned* r, uint32_t addr)
{
    asm volatile("ldmatrix.sync.aligned.m8n8.x4.shared.b16 {%0,%1,%2,%3}, [%4];"
                 : "=r"(r[0]), "=r"(r[1]), "=r"(r[2]), "=r"(r[3]) : "r"(addr));
}

#define CP_ASYNC16(dst, src) \
    asm volatile("cp.async.cg.shared.global [%0], [%1], 16;" :: "r"(dst), "l"(src))
#define CP_COMMIT() asm volatile("cp.async.commit_group;" ::: "memory")

// ---------------------------------------------------------------------------
// Prepack kernels
// ---------------------------------------------------------------------------
__global__ __launch_bounds__(256)
void prepack_x_kernel(const float* __restrict__ src,
                      __nv_bfloat16* __restrict__ hi,
                      __nv_bfloat16* __restrict__ lo)
{
    size_t i = (size_t)blockIdx.x * 256 + threadIdx.x;
    float4 v = ((const float4*)src)[i];
    __nv_bfloat16 h0, h1, h2, h3, l0, l1, l2, l3;
    split_bf16(v.x, h0, l0); split_bf16(v.y, h1, l1);
    split_bf16(v.z, h2, l2); split_bf16(v.w, h3, l3);
    ((__nv_bfloat162*)hi)[i * 2 + 0] = __nv_bfloat162(h0, h1);
    ((__nv_bfloat162*)hi)[i * 2 + 1] = __nv_bfloat162(h2, h3);
    ((__nv_bfloat162*)lo)[i * 2 + 0] = __nv_bfloat162(l0, l1);
    ((__nv_bfloat162*)lo)[i * 2 + 1] = __nv_bfloat162(l2, l3);
}

__global__ __launch_bounds__(256)
void prepack_w_kernel(const float* __restrict__ W)
{
    int k = blockIdx.x;
    const float* Wk = W + (size_t)k * C * C;
    __nv_bfloat16* oh = g_wthi + (size_t)k * C * C;
    __nv_bfloat16* ol = g_wtlo + (size_t)k * C * C;
    for (int idx = threadIdx.x; idx < C * C; idx += 256) {
        int n = idx & (C - 1);
        int cin = idx >> 7;
        float v = Wk[(size_t)cin * C + n];
        __nv_bfloat16 h, l;
        split_bf16(v, h, l);
        oh[(size_t)n * C + cin] = h;
        ol[(size_t)n * C + cin] = l;
    }
}

// ---------------------------------------------------------------------------
// Sparse conv: mma.sync + ldmatrix + cp.async double buffer.
// CTA = 128 map rows x 128 out channels; warp grid 4(M) x 2(N).
// ---------------------------------------------------------------------------
__global__ __launch_bounds__(256, 2)
void spconv_mma_kernel(const __nv_bfloat16* __restrict__ xhi,
                       const __nv_bfloat16* __restrict__ xlo,
                       const int* __restrict__ map_in,
                       const int* __restrict__ map_out,
                       float* __restrict__ acc_out)
{
    extern __shared__ __align__(16) char dynsmem[];
    float* Cs = (float*)dynsmem;          // [128][CP], aliases operand stages
    __shared__ int rowidx[BT];

    const int k    = blockIdx.y;
    const int m0   = blockIdx.x * BT;
    const int tid  = threadIdx.x;
    const int warp = tid >> 5;
    const int lane = tid & 31;
    const int wm   = warp & 3;            // M warp: 32 rows
    const int wn   = warp >> 2;           // N warp: 64 cols

    const int* mi = map_in  + (size_t)k * M_MAP + m0;
    const int* mo = map_out + (size_t)k * M_MAP + m0;
    const __nv_bfloat16* wh = g_wthi + (size_t)k * C * C;
    const __nv_bfloat16* wl = g_wtlo + (size_t)k * C * C;

    if (tid < BT) rowidx[tid] = mi[tid];
    __syncthreads();

    const uint32_t sbase = smem_u32(dynsmem);

    // --- per-thread cp.async source/dest (8 transfers per chunk) ---
    // idx = tid + it*256 (0..2047): a = idx>>9, rem = idx&511, row = rem>>2, q = rem&3
    const __nv_bfloat16* srcs[8];
    uint32_t doffs[8];
    #pragma unroll
    for (int it = 0; it < 8; it++) {
        int idx = tid + it * 256;
        int a   = idx >> 9;
        int rem = idx & 511;
        int row = rem >> 2;
        int q   = rem & 3;
        const __nv_bfloat16* s;
        if (a == 0)      s = xhi + (size_t)rowidx[row] * C;
        else if (a == 1) s = xlo + (size_t)rowidx[row] * C;
        else if (a == 2) s = wh  + (size_t)row * C;
        else             s = wl  + (size_t)row * C;
        srcs[it]  = s + q * 8;
        doffs[it] = (uint32_t)(a * ARR_SZ + row * PB + q * 16);
    }

    // --- ldmatrix per-thread addresses (offsets within a stage) ---
    const int mat = lane >> 3;            // 0..3
    const int mi8 = lane & 7;             // row within 8x8
    // A: row_off = (mat&1)*8, col_off = (mat>>1)*8
    const uint32_t aRow  = (uint32_t)(wm * 32 + (mat & 1) * 8 + mi8);
    const uint32_t aColB = (uint32_t)((mat >> 1) * 8) * 2;
    uint32_t aOff[2];                     // m-block 0/1 (hi array; +ARR_SZ for lo)
    aOff[0] = aRow * PB + aColB;
    aOff[1] = (aRow + 16) * PB + aColB;
    // B: n_off = (mat>>1)*8, col_off = (mat&1)*8
    const uint32_t bRow  = (uint32_t)(wn * 64 + (mat >> 1) * 8 + mi8);
    const uint32_t bColB = (uint32_t)((mat & 1) * 8) * 2;
    uint32_t bOff[4];                     // n-pairs 0..3 (Bhi at 2*ARR_SZ)
    #pragma unroll
    for (int p = 0; p < 4; p++)
        bOff[p] = 2 * ARR_SZ + (bRow + p * 16) * PB + bColB;

    float acc[2][8][4];
    #pragma unroll
    for (int i = 0; i < 2; i++)
        #pragma unroll
        for (int j = 0; j < 8; j++)
            #pragma unroll
            for (int q = 0; q < 4; q++) acc[i][j][q] = 0.0f;

    // ---- preload chunk 0 into stage 0 ----
    #pragma unroll
    for (int it = 0; it < 8; it++)
        CP_ASYNC16(sbase + doffs[it], srcs[it]);
    CP_COMMIT();

    for (int ch = 0; ch < NCHUNK; ch++) {
        const uint32_t stage = (uint32_t)(ch & 1) * STAGE_SZ;
        // issue loads for next chunk into other stage
        if (ch + 1 < NCHUNK) {
            const uint32_t nstage = (uint32_t)((ch + 1) & 1) * STAGE_SZ;
            const int coff = (ch + 1) * KC;
            #pragma unroll
            for (int it = 0; it < 8; it++)
                CP_ASYNC16(sbase + nstage + doffs[it], srcs[it] + coff);
            CP_COMMIT();
            asm volatile("cp.async.wait_group 1;" ::: "memory");
        } else {
            asm volatile("cp.async.wait_group 0;" ::: "memory");
        }
        __syncthreads();

        #pragma unroll
        for (int ks = 0; ks < KC / 16; ks++) {
            const uint32_t kb = (uint32_t)(ks * 16) * 2;   // byte offset of k-step
            unsigned ah[2][4], al[2][4];
            ldsm_x4(ah[0], sbase + stage + aOff[0] + kb);
            ldsm_x4(ah[1], sbase + stage + aOff[1] + kb);
            ldsm_x4(al[0], sbase + stage + ARR_SZ + aOff[0] + kb);
            ldsm_x4(al[1], sbase + stage + ARR_SZ + aOff[1] + kb);
            #pragma unroll
            for (int p = 0; p < 4; p++) {
                unsigned bh[4], bl[4];
                ldsm_x4(bh, sbase + stage + bOff[p] + kb);
                ldsm_x4(bl, sbase + stage + ARR_SZ + bOff[p] + kb);
                #pragma unroll
                for (int ns = 0; ns < 2; ns++) {
                    const int nb = p * 2 + ns;
                    #pragma unroll
                    for (int mb = 0; mb < 2; mb++) {
                        mma16816(acc[mb][nb], ah[mb], bh[ns * 2], bh[ns * 2 + 1]);
                        mma16816(acc[mb][nb], ah[mb], bl[ns * 2], bl[ns * 2 + 1]);
                        mma16816(acc[mb][nb], al[mb], bh[ns * 2], bh[ns * 2 + 1]);
                    }
                }
            }
        }
        __syncthreads();   // protect stage before next-next load overwrites
    }

    // ---- stage output tile in SMEM (fp32); Cs aliases operand buffers ----
    const int g   = lane >> 2;
    const int tig = lane & 3;
    #pragma unroll
    for (int mb = 0; mb < 2; mb++) {
        #pragma unroll
        for (int nb = 0; nb < 8; nb++) {
            int r0 = wm * 32 + mb * 16 + g;
            int cc = wn * 64 + nb * 8 + tig * 2;
            *(float2*)&Cs[r0 * CP + cc]       = make_float2(acc[mb][nb][0], acc[mb][nb][1]);
            *(float2*)&Cs[(r0 + 8) * CP + cc] = make_float2(acc[mb][nb][2], acc[mb][nb][3]);
        }
    }
    __syncthreads();

    // ---- scatter: 2 threads per row, 64 cols each, 16B vector reductions ----
    {
        int r    = tid >> 1;
        int half = tid & 1;
        int orow = mo[r];
        float* dst = acc_out + (size_t)orow * C + half * 64;
        const float* src = &Cs[r * CP + half * 64];
        #pragma unroll
        for (int j = 0; j < 16; j++) {
            float4 v = *(const float4*)(src + j * 4);
            asm volatile("red.global.v4.f32.add [%0], {%1, %2, %3, %4};"
                         :: "l"(dst + j * 4), "f"(v.x), "f"(v.y), "f"(v.z), "f"(v.w)
                         : "memory");
        }
    }
}

// ---------------------------------------------------------------------------
// BN stats / finalize
// ---------------------------------------------------------------------------
__global__ void zero_stats_kernel()
{
    int c = threadIdx.x;
    g_sum[c] = 0.0f;
    g_sq[c]  = 0.0f;
}

__global__ __launch_bounds__(256)
void bn_stats_kernel(const float* __restrict__ a)
{
    __shared__ float ss[256];
    __shared__ float sq[256];
    const int tid = threadIdx.x;
    const int c   = tid & 127;
    const int sub = tid >> 7;

    float s = 0.0f, q = 0.0f;
    for (int r = blockIdx.x * 2 + sub; r < N_PTS; r += gridDim.x * 2) {
        float v = a[(size_t)r * C + c];
        s += v;
        q += v * v;
    }
    ss[tid] = s;
    sq[tid] = q;
    __syncthreads();
    if (tid < 128) {
        atomicAdd(&g_sum[c], ss[tid] + ss[tid + 128]);
        atomicAdd(&g_sq[c],  sq[tid] + sq[tid + 128]);
    }
}

__global__ void bn_finalize_kernel(const float* __restrict__ gamma,
                                   const float* __restrict__ beta)
{
    int c = threadIdx.x;
    float m  = g_sum[c] * (1.0f / N_PTS);
    float v  = g_sq[c] * (1.0f / N_PTS) - m * m;
    float is = rsqrtf(v + EPS);
    float sc = is * gamma[c];
    g_scale[c] = sc;
    g_shift[c] = beta[c] - m * sc;
}

// ---------------------------------------------------------------------------
// Apply kernels
// ---------------------------------------------------------------------------
__device__ __forceinline__ float elu_f(float x)
{
    return x > 0.0f ? x : expm1f(x);
}

__global__ __launch_bounds__(256)
void apply_bn_elu_split_kernel(const float* __restrict__ a,
                               __nv_bfloat16* __restrict__ yh,
                               __nv_bfloat16* __restrict__ yl)
{
    size_t idx = (size_t)blockIdx.x * 256 + threadIdx.x;
    int c4 = (int)(idx & 31);
    float4 v  = ((const float4*)a)[idx];
    float4 sc = ((const float4*)g_scale)[c4];
    float4 sh = ((const float4*)g_shift)[c4];
    float4 r;
    r.x = elu_f(fmaf(v.x, sc.x, sh.x));
    r.y = elu_f(fmaf(v.y, sc.y, sh.y));
    r.z = elu_f(fmaf(v.z, sc.z, sh.z));
    r.w = elu_f(fmaf(v.w, sc.w, sh.w));
    __nv_bfloat16 h0, h1, h2, h3, l0, l1, l2, l3;
    split_bf16(r.x, h0, l0); split_bf16(r.y, h1, l1);
    split_bf16(r.z, h2, l2); split_bf16(r.w, h3, l3);
    ((__nv_bfloat162*)yh)[idx * 2 + 0] = __nv_bfloat162(h0, h1);
    ((__nv_bfloat162*)yh)[idx * 2 + 1] = __nv_bfloat162(h2, h3);
    ((__nv_bfloat162*)yl)[idx * 2 + 0] = __nv_bfloat162(l0, l1);
    ((__nv_bfloat162*)yl)[idx * 2 + 1] = __nv_bfloat162(l2, l3);
}

__global__ __launch_bounds__(256)
void apply_bn_res_elu_kernel(const float* __restrict__ a,
                             const float* __restrict__ resid,
                             float* __restrict__ o)
{
    size_t idx = (size_t)blockIdx.x * 256 + threadIdx.x;
    int c4 = (int)(idx & 31);
    float4 v  = ((const float4*)a)[idx];
    float4 rs = ((const float4*)resid)[idx];
    float4 sc = ((const float4*)g_scale)[c4];
    float4 sh = ((const float4*)g_shift)[c4];
    float4 r;
    r.x = elu_f(fmaf(v.x, sc.x, sh.x) + rs.x);
    r.y = elu_f(fmaf(v.y, sc.y, sh.y) + rs.y);
    r.z = elu_f(fmaf(v.z, sc.z, sh.z) + rs.z);
    r.w = elu_f(fmaf(v.w, sc.w, sh.w) + rs.w);
    ((float4*)o)[idx] = r;
}

// ---------------------------------------------------------------------------
// Launch
// ---------------------------------------------------------------------------
extern "C" void kernel_launch(void* const* d_in, const int* in_sizes, int n_in,
                              void* d_out, int out_size)
{
    const float* x       = (const float*)d_in[0];
    const float* W1      = (const float*)d_in[1];
    const float* gamma1  = (const float*)d_in[2];
    const float* beta1   = (const float*)d_in[3];
    const float* W2      = (const float*)d_in[4];
    const float* gamma2  = (const float*)d_in[5];
    const float* beta2   = (const float*)d_in[6];
    const int*   map1_in  = (const int*)d_in[7];
    const int*   map1_out = (const int*)d_in[8];
    const int*   map2_in  = (const int*)d_in[9];
    const int*   map2_out = (const int*)d_in[10];
    float* out = (float*)d_out;

    void *accPtr, *xhiPtr, *xloPtr, *yhiPtr, *yloPtr;
    cudaGetSymbolAddress(&accPtr, g_acc);
    cudaGetSymbolAddress(&xhiPtr, g_xhi);
    cudaGetSymbolAddress(&xloPtr, g_xlo);
    cudaGetSymbolAddress(&yhiPtr, g_yhi);
    cudaGetSymbolAddress(&yloPtr, g_ylo);
    const size_t accBytes = (size_t)N_PTS * C * sizeof(float);

    cudaFuncSetAttribute(spconv_mma_kernel,
                         cudaFuncAttributeMaxDynamicSharedMemorySize, DYN_SMEM);

    const dim3 convGrid(M_MAP / BT, KNUM);
    const int  elem4  = (N_PTS * C) / 4;
    const int  ewGrid = elem4 / 256;

    // ---- prepack ----
    prepack_x_kernel<<<ewGrid, 256>>>(x, (__nv_bfloat16*)xhiPtr, (__nv_bfloat16*)xloPtr);
    prepack_w_kernel<<<KNUM, 256>>>(W1);
    cudaMemsetAsync(accPtr, 0, accBytes);
    zero_stats_kernel<<<1, C>>>();

    // ---- layer 1 ----
    spconv_mma_kernel<<<convGrid, 256, DYN_SMEM>>>(
        (const __nv_bfloat16*)xhiPtr, (const __nv_bfloat16*)xloPtr,
        map1_in, map1_out, (float*)accPtr);
    bn_stats_kernel<<<256, 256>>>((const float*)accPtr);
    bn_finalize_kernel<<<1, C>>>(gamma1, beta1);
    apply_bn_elu_split_kernel<<<ewGrid, 256>>>(
        (const float*)accPtr, (__nv_bfloat16*)yhiPtr, (__nv_bfloat16*)yloPtr);

    // ---- layer 2 ----
    prepack_w_kernel<<<KNUM, 256>>>(W2);
    cudaMemsetAsync(accPtr, 0, accBytes);
    zero_stats_kernel<<<1, C>>>();
    spconv_mma_kernel<<<convGrid, 256, DYN_SMEM>>>(
        (const __nv_bfloat16*)yhiPtr, (const __nv_bfloat16*)yloPtr,
        map2_in, map2_out, (float*)accPtr);
    bn_stats_kernel<<<256, 256>>>((const float*)accPtr);
    bn_finalize_kernel<<<1, C>>>(gamma2, beta2);
    apply_bn_res_elu_kernel<<<ewGrid, 256>>>((const float*)accPtr, x, out);
}

// round 7
// speedup vs baseline: 2.0620x; 1.0306x over previous
#include <cuda_runtime.h>
#include <cuda_bf16.h>
#include <math.h>
#include <stdint.h>

#define N_PTS 131072
#define C 128
#define KNUM 27
#define M_MAP 65536
#define EPS 1e-5f

#define BT 128            // map rows per CTA tile
#define KC 32             // k-elems per chunk
#define NCHUNK (C / KC)   // 4
#define PB 80             // smem row pitch in BYTES (40 bf16) — LDSM conflict-free
#define ARR_SZ (BT * PB)  // 10240 B per operand array
#define STAGE_SZ (4 * ARR_SZ)   // Ahi, Alo, Bhi, Blo = 40960 B
#define DYN_SMEM (2 * STAGE_SZ) // 81920 B (2 stages); Cs (67584 B) aliases this
#define CP 132            // output stage pitch in floats

// ---- scratch (static device allocations; allowed) ----
__device__ __align__(16) float         g_acc[(size_t)N_PTS * C];
__device__ __align__(16) __nv_bfloat16 g_xhi[(size_t)N_PTS * C];
__device__ __align__(16) __nv_bfloat16 g_xlo[(size_t)N_PTS * C];
__device__ __align__(16) __nv_bfloat16 g_yhi[(size_t)N_PTS * C];
__device__ __align__(16) __nv_bfloat16 g_ylo[(size_t)N_PTS * C];
__device__ __align__(16) __nv_bfloat16 g_wthi[(size_t)KNUM * C * C]; // W^T: [k][n][cin]
__device__ __align__(16) __nv_bfloat16 g_wtlo[(size_t)KNUM * C * C];
__device__ __align__(16) float g_sum[C];
__device__ __align__(16) float g_sq[C];
__device__ __align__(16) float g_scale[C];
__device__ __align__(16) float g_shift[C];

// ---------------------------------------------------------------------------
// helpers
// ---------------------------------------------------------------------------
__device__ __forceinline__ uint32_t smem_u32(const void* p)
{
    uint32_t a;
    asm("{ .reg .u64 t; cvta.to.shared.u64 t, %1; cvt.u32.u64 %0, t; }"
        : "=r"(a) : "l"(p));
    return a;
}

__device__ __forceinline__ void split_bf16(float v, __nv_bfloat16& h, __nv_bfloat16& l)
{
    h = __float2bfloat16_rn(v);
    l = __float2bfloat16_rn(v - __bfloat162float(h));
}

__device__ __forceinline__ void mma16816(float* c, const unsigned* a,
                                         unsigned b0, unsigned b1)
{
    asm volatile(
        "mma.sync.aligned.m16n8k16.row.col.f32.bf16.bf16.f32 "
        "{%0,%1,%2,%3}, {%4,%5,%6,%7}, {%8,%9}, {%0,%1,%2,%3};"
        : "+f"(c[0]), "+f"(c[1]), "+f"(c[2]), "+f"(c[3])
        : "r"(a[0]), "r"(a[1]), "r"(a[2]), "r"(a[3]), "r"(b0), "r"(b1));
}

__device__ __forceinline__ void ldsm_x4(unsigned* r, uint32_t addr)
{
    asm volatile("ldmatrix.sync.aligned.m8n8.x4.shared.b16 {%0,%1,%2,%3}, [%4];"
                 : "=r"(r[0]), "=r"(r[1]), "=r"(r[2]), "=r"(r[3]) : "r"(addr));
}

#define CP_ASYNC16(dst, src) \
    asm volatile("cp.async.cg.shared.global [%0], [%1], 16;" :: "r"(dst), "l"(src))
#define CP_COMMIT() asm volatile("cp.async.commit_group;" ::: "memory")

// ---------------------------------------------------------------------------
// Prepack kernels
// ---------------------------------------------------------------------------
__global__ __launch_bounds__(256)
void prepack_x_kernel(const float* __restrict__ src,
                      __nv_bfloat16* __restrict__ hi,
                      __nv_bfloat16* __restrict__ lo)
{
    size_t i = (size_t)blockIdx.x * 256 + threadIdx.x;
    float4 v = ((const float4*)src)[i];
    __nv_bfloat16 h0, h1, h2, h3, l0, l1, l2, l3;
    split_bf16(v.x, h0, l0); split_bf16(v.y, h1, l1);
    split_bf16(v.z, h2, l2); split_bf16(v.w, h3, l3);
    ((__nv_bfloat162*)hi)[i * 2 + 0] = __nv_bfloat162(h0, h1);
    ((__nv_bfloat162*)hi)[i * 2 + 1] = __nv_bfloat162(h2, h3);
    ((__nv_bfloat162*)lo)[i * 2 + 0] = __nv_bfloat162(l0, l1);
    ((__nv_bfloat162*)lo)[i * 2 + 1] = __nv_bfloat162(l2, l3);
}

__global__ __launch_bounds__(256)
void prepack_w_kernel(const float* __restrict__ W)
{
    int k = blockIdx.x;
    const float* Wk = W + (size_t)k * C * C;
    __nv_bfloat16* oh = g_wthi + (size_t)k * C * C;
    __nv_bfloat16* ol = g_wtlo + (size_t)k * C * C;
    for (int idx = threadIdx.x; idx < C * C; idx += 256) {
        int n = idx & (C - 1);
        int cin = idx >> 7;
        float v = Wk[(size_t)cin * C + n];
        __nv_bfloat16 h, l;
        split_bf16(v, h, l);
        oh[(size_t)n * C + cin] = h;
        ol[(size_t)n * C + cin] = l;
    }
}

// ---------------------------------------------------------------------------
// Sparse conv: mma.sync + ldmatrix + cp.async double buffer.
// CTA = 128 map rows x 128 out channels; 4 warps, warp tile 64M x 64N.
// ---------------------------------------------------------------------------
__global__ __launch_bounds__(128, 2)
void spconv_mma_kernel(const __nv_bfloat16* __restrict__ xhi,
                       const __nv_bfloat16* __restrict__ xlo,
                       const int* __restrict__ map_in,
                       const int* __restrict__ map_out,
                       float* __restrict__ acc_out)
{
    extern __shared__ __align__(16) char dynsmem[];
    float* Cs = (float*)dynsmem;          // [128][CP], aliases operand stages
    __shared__ int rowidx[BT];

    const int k    = blockIdx.y;
    const int m0   = blockIdx.x * BT;
    const int tid  = threadIdx.x;
    const int warp = tid >> 5;
    const int lane = tid & 31;
    const int wm   = warp & 1;            // M warp: 64 rows
    const int wn   = warp >> 1;           // N warp: 64 cols

    const int* mi = map_in  + (size_t)k * M_MAP + m0;
    const int* mo = map_out + (size_t)k * M_MAP + m0;
    const __nv_bfloat16* wh = g_wthi + (size_t)k * C * C;
    const __nv_bfloat16* wl = g_wtlo + (size_t)k * C * C;

    rowidx[tid] = mi[tid];
    __syncthreads();

    const uint32_t sbase = smem_u32(dynsmem);

    // --- cp.async addressing: thread handles rows r0t + j*32, granule q ---
    const int q   = tid & 3;
    const int r0t = tid >> 2;             // 0..31
    size_t px[4];
    #pragma unroll
    for (int j = 0; j < 4; j++)
        px[j] = (size_t)rowidx[r0t + j * 32] * C;

    // --- ldmatrix per-thread offsets (within a stage) ---
    const int mat = lane >> 3;            // 0..3
    const int mi8 = lane & 7;
    uint32_t aOff[4];                     // A m-blocks (hi array; +ARR_SZ for lo)
    #pragma unroll
    for (int mb = 0; mb < 4; mb++)
        aOff[mb] = (uint32_t)((wm * 64 + mb * 16 + (mat & 1) * 8 + mi8) * PB
                              + (mat >> 1) * 16);
    uint32_t bOff[4];                     // B n-pairs (Bhi at 2*ARR_SZ)
    #pragma unroll
    for (int p = 0; p < 4; p++)
        bOff[p] = (uint32_t)(2 * ARR_SZ
                             + (wn * 64 + p * 16 + (mat >> 1) * 8 + mi8) * PB
                             + (mat & 1) * 16);

    float acc[4][8][4];
    #pragma unroll
    for (int i = 0; i < 4; i++)
        #pragma unroll
        for (int j = 0; j < 8; j++)
            #pragma unroll
            for (int t = 0; t < 4; t++) acc[i][j][t] = 0.0f;

    // ---- preload chunk 0 into stage 0 ----
    #pragma unroll
    for (int j = 0; j < 4; j++) {
        int row = r0t + j * 32;
        uint32_t d = sbase + (uint32_t)(row * PB + q * 16);
        CP_ASYNC16(d,               xhi + px[j] + q * 8);
        CP_ASYNC16(d + ARR_SZ,      xlo + px[j] + q * 8);
        CP_ASYNC16(d + 2 * ARR_SZ,  wh + (size_t)row * C + q * 8);
        CP_ASYNC16(d + 3 * ARR_SZ,  wl + (size_t)row * C + q * 8);
    }
    CP_COMMIT();

    for (int ch = 0; ch < NCHUNK; ch++) {
        const uint32_t stage = (uint32_t)(ch & 1) * STAGE_SZ;
        if (ch + 1 < NCHUNK) {
            const uint32_t nstage = (uint32_t)((ch + 1) & 1) * STAGE_SZ;
            const int coff = (ch + 1) * KC;
            #pragma unroll
            for (int j = 0; j < 4; j++) {
                int row = r0t + j * 32;
                uint32_t d = sbase + nstage + (uint32_t)(row * PB + q * 16);
                CP_ASYNC16(d,               xhi + px[j] + coff + q * 8);
                CP_ASYNC16(d + ARR_SZ,      xlo + px[j] + coff + q * 8);
                CP_ASYNC16(d + 2 * ARR_SZ,  wh + (size_t)row * C + coff + q * 8);
                CP_ASYNC16(d + 3 * ARR_SZ,  wl + (size_t)row * C + coff + q * 8);
            }
            CP_COMMIT();
            asm volatile("cp.async.wait_group 1;" ::: "memory");
        } else {
            asm volatile("cp.async.wait_group 0;" ::: "memory");
        }
        __syncthreads();

        #pragma unroll
        for (int ks = 0; ks < KC / 16; ks++) {
            const uint32_t kb = (uint32_t)(ks * 32);   // 16 bf16 = 32 B
            unsigned ah[4][4], al[4][4];
            #pragma unroll
            for (int mb = 0; mb < 4; mb++) {
                ldsm_x4(ah[mb], sbase + stage + aOff[mb] + kb);
                ldsm_x4(al[mb], sbase + stage + ARR_SZ + aOff[mb] + kb);
            }
            #pragma unroll
            for (int p = 0; p < 4; p++) {
                unsigned bh[4], bl[4];
                ldsm_x4(bh, sbase + stage + bOff[p] + kb);
                ldsm_x4(bl, sbase + stage + ARR_SZ + bOff[p] + kb);
                #pragma unroll
                for (int ns = 0; ns < 2; ns++) {
                    const int nb = p * 2 + ns;
                    #pragma unroll
                    for (int mb = 0; mb < 4; mb++) {
                        mma16816(acc[mb][nb], ah[mb], bh[ns * 2], bh[ns * 2 + 1]);
                        mma16816(acc[mb][nb], ah[mb], bl[ns * 2], bl[ns * 2 + 1]);
                        mma16816(acc[mb][nb], al[mb], bh[ns * 2], bh[ns * 2 + 1]);
                    }
                }
            }
        }
        __syncthreads();
    }

    // ---- stage output tile in SMEM (fp32); Cs aliases operand buffers ----
    const int g   = lane >> 2;
    const int tig = lane & 3;
    #pragma unroll
    for (int mb = 0; mb < 4; mb++) {
        #pragma unroll
        for (int nb = 0; nb < 8; nb++) {
            int r0 = wm * 64 + mb * 16 + g;
            int cc = wn * 64 + nb * 8 + tig * 2;
            *(float2*)&Cs[r0 * CP + cc]       = make_float2(acc[mb][nb][0], acc[mb][nb][1]);
            *(float2*)&Cs[(r0 + 8) * CP + cc] = make_float2(acc[mb][nb][2], acc[mb][nb][3]);
        }
    }
    __syncthreads();

    // ---- scatter: 8 threads per row (contiguous 128B segments), 16 rows/iter ----
    {
        const int sub = tid & 7;              // 16B granule group within row
        const int rg  = tid >> 3;             // 0..15
        #pragma unroll
        for (int iter = 0; iter < 8; iter++) {
            int r    = iter * 16 + rg;
            int orow = mo[r];
            float* dst = acc_out + (size_t)orow * C + sub * 16;
            const float* src = &Cs[r * CP + sub * 16];
            #pragma unroll
            for (int j = 0; j < 4; j++) {
                float4 v = *(const float4*)(src + j * 4);
                asm volatile("red.global.v4.f32.add [%0], {%1, %2, %3, %4};"
                             :: "l"(dst + j * 4), "f"(v.x), "f"(v.y), "f"(v.z), "f"(v.w)
                             : "memory");
            }
        }
    }
}

// ---------------------------------------------------------------------------
// BN stats / finalize
// ---------------------------------------------------------------------------
__global__ void zero_stats_kernel()
{
    int c = threadIdx.x;
    g_sum[c] = 0.0f;
    g_sq[c]  = 0.0f;
}

__global__ __launch_bounds__(256)
void bn_stats_kernel(const float* __restrict__ a)
{
    __shared__ float4 ss[256];
    __shared__ float4 qq[256];
    const int tid = threadIdx.x;
    const int c4  = tid & 31;                 // float4 group within row
    const int ro  = tid >> 5;                 // 0..7

    float4 s = make_float4(0.f, 0.f, 0.f, 0.f);
    float4 p = make_float4(0.f, 0.f, 0.f, 0.f);
    for (int r = blockIdx.x * 8 + ro; r < N_PTS; r += gridDim.x * 8) {
        float4 v = ((const float4*)a)[(size_t)r * 32 + c4];
        s.x += v.x; s.y += v.y; s.z += v.z; s.w += v.w;
        p.x += v.x * v.x; p.y += v.y * v.y; p.z += v.z * v.z; p.w += v.w * v.w;
    }
    ss[tid] = s;
    qq[tid] = p;
    __syncthreads();
    if (tid < 32) {
        float4 S = ss[tid], Q = qq[tid];
        #pragma unroll
        for (int j = 1; j < 8; j++) {
            float4 s2 = ss[tid + j * 32], q2 = qq[tid + j * 32];
            S.x += s2.x; S.y += s2.y; S.z += s2.z; S.w += s2.w;
            Q.x += q2.x; Q.y += q2.y; Q.z += q2.z; Q.w += q2.w;
        }
        atomicAdd(&g_sum[tid * 4 + 0], S.x);
        atomicAdd(&g_sum[tid * 4 + 1], S.y);
        atomicAdd(&g_sum[tid * 4 + 2], S.z);
        atomicAdd(&g_sum[tid * 4 + 3], S.w);
        atomicAdd(&g_sq[tid * 4 + 0], Q.x);
        atomicAdd(&g_sq[tid * 4 + 1], Q.y);
        atomicAdd(&g_sq[tid * 4 + 2], Q.z);
        atomicAdd(&g_sq[tid * 4 + 3], Q.w);
    }
}

__global__ void bn_finalize_kernel(const float* __restrict__ gamma,
                                   const float* __restrict__ beta)
{
    int c = threadIdx.x;
    float m  = g_sum[c] * (1.0f / N_PTS);
    float v  = g_sq[c] * (1.0f / N_PTS) - m * m;
    float is = rsqrtf(v + EPS);
    float sc = is * gamma[c];
    g_scale[c] = sc;
    g_shift[c] = beta[c] - m * sc;
}

// ---------------------------------------------------------------------------
// Apply kernels
// ---------------------------------------------------------------------------
__device__ __forceinline__ float elu_f(float x)
{
    return x > 0.0f ? x : expm1f(x);
}

__global__ __launch_bounds__(256)
void apply_bn_elu_split_kernel(const float* __restrict__ a,
                               __nv_bfloat16* __restrict__ yh,
                               __nv_bfloat16* __restrict__ yl)
{
    size_t idx = (size_t)blockIdx.x * 256 + threadIdx.x;
    int c4 = (int)(idx & 31);
    float4 v  = ((const float4*)a)[idx];
    float4 sc = ((const float4*)g_scale)[c4];
    float4 sh = ((const float4*)g_shift)[c4];
    float4 r;
    r.x = elu_f(fmaf(v.x, sc.x, sh.x));
    r.y = elu_f(fmaf(v.y, sc.y, sh.y));
    r.z = elu_f(fmaf(v.z, sc.z, sh.z));
    r.w = elu_f(fmaf(v.w, sc.w, sh.w));
    __nv_bfloat16 h0, h1, h2, h3, l0, l1, l2, l3;
    split_bf16(r.x, h0, l0); split_bf16(r.y, h1, l1);
    split_bf16(r.z, h2, l2); split_bf16(r.w, h3, l3);
    ((__nv_bfloat162*)yh)[idx * 2 + 0] = __nv_bfloat162(h0, h1);
    ((__nv_bfloat162*)yh)[idx * 2 + 1] = __nv_bfloat162(h2, h3);
    ((__nv_bfloat162*)yl)[idx * 2 + 0] = __nv_bfloat162(l0, l1);
    ((__nv_bfloat162*)yl)[idx * 2 + 1] = __nv_bfloat162(l2, l3);
}

__global__ __launch_bounds__(256)
void apply_bn_res_elu_kernel(const float* __restrict__ a,
                             const float* __restrict__ resid,
                             float* __restrict__ o)
{
    size_t idx = (size_t)blockIdx.x * 256 + threadIdx.x;
    int c4 = (int)(idx & 31);
    float4 v  = ((const float4*)a)[idx];
    float4 rs = ((const float4*)resid)[idx];
    float4 sc = ((const float4*)g_scale)[c4];
    float4 sh = ((const float4*)g_shift)[c4];
    float4 r;
    r.x = elu_f(fmaf(v.x, sc.x, sh.x) + rs.x);
    r.y = elu_f(fmaf(v.y, sc.y, sh.y) + rs.y);
    r.z = elu_f(fmaf(v.z, sc.z, sh.z) + rs.z);
    r.w = elu_f(fmaf(v.w, sc.w, sh.w) + rs.w);
    ((float4*)o)[idx] = r;
}

// ---------------------------------------------------------------------------
// Launch
// ---------------------------------------------------------------------------
extern "C" void kernel_launch(void* const* d_in, const int* in_sizes, int n_in,
                              void* d_out, int out_size)
{
    const float* x       = (const float*)d_in[0];
    const float* W1      = (const float*)d_in[1];
    const float* gamma1  = (const float*)d_in[2];
    const float* beta1   = (const float*)d_in[3];
    const float* W2      = (const float*)d_in[4];
    const float* gamma2  = (const float*)d_in[5];
    const float* beta2   = (const float*)d_in[6];
    const int*   map1_in  = (const int*)d_in[7];
    const int*   map1_out = (const int*)d_in[8];
    const int*   map2_in  = (const int*)d_in[9];
    const int*   map2_out = (const int*)d_in[10];
    float* out = (float*)d_out;

    void *accPtr, *xhiPtr, *xloPtr, *yhiPtr, *yloPtr;
    cudaGetSymbolAddress(&accPtr, g_acc);
    cudaGetSymbolAddress(&xhiPtr, g_xhi);
    cudaGetSymbolAddress(&xloPtr, g_xlo);
    cudaGetSymbolAddress(&yhiPtr, g_yhi);
    cudaGetSymbolAddress(&yloPtr, g_ylo);
    const size_t accBytes = (size_t)N_PTS * C * sizeof(float);

    cudaFuncSetAttribute(spconv_mma_kernel,
                         cudaFuncAttributeMaxDynamicSharedMemorySize, DYN_SMEM);

    const dim3 convGrid(M_MAP / BT, KNUM);
    const int  elem4  = (N_PTS * C) / 4;
    const int  ewGrid = elem4 / 256;

    // ---- prepack ----
    prepack_x_kernel<<<ewGrid, 256>>>(x, (__nv_bfloat16*)xhiPtr, (__nv_bfloat16*)xloPtr);
    prepack_w_kernel<<<KNUM, 256>>>(W1);
    cudaMemsetAsync(accPtr, 0, accBytes);
    zero_stats_kernel<<<1, C>>>();

    // ---- layer 1 ----
    spconv_mma_kernel<<<convGrid, 128, DYN_SMEM>>>(
        (const __nv_bfloat16*)xhiPtr, (const __nv_bfloat16*)xloPtr,
        map1_in, map1_out, (float*)accPtr);
    bn_stats_kernel<<<256, 256>>>((const float*)accPtr);
    bn_finalize_kernel<<<1, C>>>(gamma1, beta1);
    apply_bn_elu_split_kernel<<<ewGrid, 256>>>(
        (const float*)accPtr, (__nv_bfloat16*)yhiPtr, (__nv_bfloat16*)yloPtr);

    // ---- layer 2 ----
    prepack_w_kernel<<<KNUM, 256>>>(W2);
    cudaMemsetAsync(accPtr, 0, accBytes);
    zero_stats_kernel<<<1, C>>>();
    spconv_mma_kernel<<<convGrid, 128, DYN_SMEM>>>(
        (const __nv_bfloat16*)yhiPtr, (const __nv_bfloat16*)yloPtr,
        map2_in, map2_out, (float*)accPtr);
    bn_stats_kernel<<<256, 256>>>((const float*)accPtr);
    bn_finalize_kernel<<<1, C>>>(gamma2, beta2);
    apply_bn_res_elu_kernel<<<ewGrid, 256>>>((const float*)accPtr, x, out);
}

// round 8
// speedup vs baseline: 2.4491x; 1.1877x over previous
#include <cuda_runtime.h>
#include <cuda_bf16.h>
#include <math.h>
#include <stdint.h>

#define N_PTS 131072
#define C 128
#define KNUM 27
#define M_MAP 65536
#define EPS 1e-5f

#define BT 128            // map rows per CTA tile
#define KC 32             // k-elems per chunk
#define NCHUNK (C / KC)   // 4
#define PB 80             // smem row pitch in BYTES (40 bf16) — LDSM conflict-free
#define ARR_SZ (BT * PB)  // 10240 B per operand array
#define STAGE_SZ (4 * ARR_SZ)   // Ahi, Alo, Bhi, Blo = 40960 B
#define DYN_SMEM (2 * STAGE_SZ) // 81920 B (2 stages)

// ---- scratch (static device allocations; allowed) ----
__device__ __align__(16) float         g_acc[(size_t)N_PTS * C];
__device__ __align__(16) __nv_bfloat16 g_xhi[(size_t)N_PTS * C];
__device__ __align__(16) __nv_bfloat16 g_xlo[(size_t)N_PTS * C];
__device__ __align__(16) __nv_bfloat16 g_yhi[(size_t)N_PTS * C];
__device__ __align__(16) __nv_bfloat16 g_ylo[(size_t)N_PTS * C];
__device__ __align__(16) __nv_bfloat16 g_wthi[(size_t)KNUM * C * C]; // W^T: [k][n][cin]
__device__ __align__(16) __nv_bfloat16 g_wtlo[(size_t)KNUM * C * C];
__device__ __align__(16) float g_sum[C];
__device__ __align__(16) float g_sq[C];
__device__ __align__(16) float g_scale[C];
__device__ __align__(16) float g_shift[C];

// ---------------------------------------------------------------------------
// helpers
// ---------------------------------------------------------------------------
__device__ __forceinline__ uint32_t smem_u32(const void* p)
{
    uint32_t a;
    asm("{ .reg .u64 t; cvta.to.shared.u64 t, %1; cvt.u32.u64 %0, t; }"
        : "=r"(a) : "l"(p));
    return a;
}

__device__ __forceinline__ void split_bf16(float v, __nv_bfloat16& h, __nv_bfloat16& l)
{
    h = __float2bfloat16_rn(v);
    l = __float2bfloat16_rn(v - __bfloat162float(h));
}

__device__ __forceinline__ void mma16816(float* c, const unsigned* a,
                                         unsigned b0, unsigned b1)
{
    asm volatile(
        "mma.sync.aligned.m16n8k16.row.col.f32.bf16.bf16.f32 "
        "{%0,%1,%2,%3}, {%4,%5,%6,%7}, {%8,%9}, {%0,%1,%2,%3};"
        : "+f"(c[0]), "+f"(c[1]), "+f"(c[2]), "+f"(c[3])
        : "r"(a[0]), "r"(a[1]), "r"(a[2]), "r"(a[3]), "r"(b0), "r"(b1));
}

__device__ __forceinline__ void ldsm_x4(unsigned* r, uint32_t addr)
{
    asm volatile("ldmatrix.sync.aligned.m8n8.x4.shared.b16 {%0,%1,%2,%3}, [%4];"
                 : "=r"(r[0]), "=r"(r[1]), "=r"(r[2]), "=r"(r[3]) : "r"(addr));
}

#define CP_ASYNC16(dst, src) \
    asm volatile("cp.async.cg.shared.global [%0], [%1], 16;" :: "r"(dst), "l"(src))
#define CP_COMMIT() asm volatile("cp.async.commit_group;" ::: "memory")

// ---------------------------------------------------------------------------
// Prepack kernels
// ---------------------------------------------------------------------------
__global__ __launch_bounds__(256)
void prepack_x_kernel(const float* __restrict__ src,
                      __nv_bfloat16* __restrict__ hi,
                      __nv_bfloat16* __restrict__ lo)
{
    size_t i = (size_t)blockIdx.x * 256 + threadIdx.x;
    float4 v = ((const float4*)src)[i];
    __nv_bfloat16 h0, h1, h2, h3, l0, l1, l2, l3;
    split_bf16(v.x, h0, l0); split_bf16(v.y, h1, l1);
    split_bf16(v.z, h2, l2); split_bf16(v.w, h3, l3);
    ((__nv_bfloat162*)hi)[i * 2 + 0] = __nv_bfloat162(h0, h1);
    ((__nv_bfloat162*)hi)[i * 2 + 1] = __nv_bfloat162(h2, h3);
    ((__nv_bfloat162*)lo)[i * 2 + 0] = __nv_bfloat162(l0, l1);
    ((__nv_bfloat162*)lo)[i * 2 + 1] = __nv_bfloat162(l2, l3);
}

__global__ __launch_bounds__(256)
void prepack_w_kernel(const float* __restrict__ W)
{
    int k = blockIdx.x;
    const float* Wk = W + (size_t)k * C * C;
    __nv_bfloat16* oh = g_wthi + (size_t)k * C * C;
    __nv_bfloat16* ol = g_wtlo + (size_t)k * C * C;
    for (int idx = threadIdx.x; idx < C * C; idx += 256) {
        int n = idx & (C - 1);
        int cin = idx >> 7;
        float v = Wk[(size_t)cin * C + n];
        __nv_bfloat16 h, l;
        split_bf16(v, h, l);
        oh[(size_t)n * C + cin] = h;
        ol[(size_t)n * C + cin] = l;
    }
}

// ---------------------------------------------------------------------------
// Sparse conv: mma.sync + ldmatrix + cp.async double buffer.
// CTA = 128 map rows x 128 out channels; 8 warps, warp tile 32M x 64N.
// Epilogue: shfl-swap to 4-col runs, direct red.global.v4 from registers.
// ---------------------------------------------------------------------------
__global__ __launch_bounds__(256, 2)
void spconv_mma_kernel(const __nv_bfloat16* __restrict__ xhi,
                       const __nv_bfloat16* __restrict__ xlo,
                       const int* __restrict__ map_in,
                       const int* __restrict__ map_out,
                       float* __restrict__ acc_out)
{
    extern __shared__ __align__(16) char dynsmem[];
    __shared__ int rowidx[BT];

    const int k    = blockIdx.y;
    const int m0   = blockIdx.x * BT;
    const int tid  = threadIdx.x;
    const int warp = tid >> 5;
    const int lane = tid & 31;
    const int wm   = warp & 3;            // M warp: 32 rows
    const int wn   = warp >> 2;           // N warp: 64 cols

    const int* mi = map_in  + (size_t)k * M_MAP + m0;
    const int* mo = map_out + (size_t)k * M_MAP + m0;
    const __nv_bfloat16* wh = g_wthi + (size_t)k * C * C;
    const __nv_bfloat16* wl = g_wtlo + (size_t)k * C * C;

    if (tid < BT) rowidx[tid] = mi[tid];
    __syncthreads();

    const uint32_t sbase = smem_u32(dynsmem);

    // --- per-thread cp.async source/dest (8 transfers per chunk) ---
    const __nv_bfloat16* srcs[8];
    uint32_t doffs[8];
    #pragma unroll
    for (int it = 0; it < 8; it++) {
        int idx = tid + it * 256;
        int a   = idx >> 9;
        int rem = idx & 511;
        int row = rem >> 2;
        int q   = rem & 3;
        const __nv_bfloat16* s;
        if (a == 0)      s = xhi + (size_t)rowidx[row] * C;
        else if (a == 1) s = xlo + (size_t)rowidx[row] * C;
        else if (a == 2) s = wh  + (size_t)row * C;
        else             s = wl  + (size_t)row * C;
        srcs[it]  = s + q * 8;
        doffs[it] = (uint32_t)(a * ARR_SZ + row * PB + q * 16);
    }

    // --- ldmatrix per-thread offsets (within a stage) ---
    const int mat = lane >> 3;            // 0..3
    const int mi8 = lane & 7;
    const uint32_t aRow  = (uint32_t)(wm * 32 + (mat & 1) * 8 + mi8);
    const uint32_t aColB = (uint32_t)((mat >> 1) * 8) * 2;
    uint32_t aOff[2];
    aOff[0] = aRow * PB + aColB;
    aOff[1] = (aRow + 16) * PB + aColB;
    const uint32_t bRow  = (uint32_t)(wn * 64 + (mat >> 1) * 8 + mi8);
    const uint32_t bColB = (uint32_t)((mat & 1) * 8) * 2;
    uint32_t bOff[4];
    #pragma unroll
    for (int p = 0; p < 4; p++)
        bOff[p] = 2 * ARR_SZ + (bRow + p * 16) * PB + bColB;

    float acc[2][8][4];
    #pragma unroll
    for (int i = 0; i < 2; i++)
        #pragma unroll
        for (int j = 0; j < 8; j++)
            #pragma unroll
            for (int t = 0; t < 4; t++) acc[i][j][t] = 0.0f;

    // ---- preload chunk 0 into stage 0 ----
    #pragma unroll
    for (int it = 0; it < 8; it++)
        CP_ASYNC16(sbase + doffs[it], srcs[it]);
    CP_COMMIT();

    for (int ch = 0; ch < NCHUNK; ch++) {
        const uint32_t stage = (uint32_t)(ch & 1) * STAGE_SZ;
        if (ch + 1 < NCHUNK) {
            const uint32_t nstage = (uint32_t)((ch + 1) & 1) * STAGE_SZ;
            const int coff = (ch + 1) * KC;
            #pragma unroll
            for (int it = 0; it < 8; it++)
                CP_ASYNC16(sbase + nstage + doffs[it], srcs[it] + coff);
            CP_COMMIT();
            asm volatile("cp.async.wait_group 1;" ::: "memory");
        } else {
            asm volatile("cp.async.wait_group 0;" ::: "memory");
        }
        __syncthreads();

        #pragma unroll
        for (int ks = 0; ks < KC / 16; ks++) {
            const uint32_t kb = (uint32_t)(ks * 32);
            unsigned ah[2][4], al[2][4];
            ldsm_x4(ah[0], sbase + stage + aOff[0] + kb);
            ldsm_x4(ah[1], sbase + stage + aOff[1] + kb);
            ldsm_x4(al[0], sbase + stage + ARR_SZ + aOff[0] + kb);
            ldsm_x4(al[1], sbase + stage + ARR_SZ + aOff[1] + kb);
            #pragma unroll
            for (int p = 0; p < 4; p++) {
                unsigned bh[4], bl[4];
                ldsm_x4(bh, sbase + stage + bOff[p] + kb);
                ldsm_x4(bl, sbase + stage + ARR_SZ + bOff[p] + kb);
                #pragma unroll
                for (int ns = 0; ns < 2; ns++) {
                    const int nb = p * 2 + ns;
                    #pragma unroll
                    for (int mb = 0; mb < 2; mb++) {
                        mma16816(acc[mb][nb], ah[mb], bh[ns * 2], bh[ns * 2 + 1]);
                        mma16816(acc[mb][nb], ah[mb], bl[ns * 2], bl[ns * 2 + 1]);
                        mma16816(acc[mb][nb], al[mb], bh[ns * 2], bh[ns * 2 + 1]);
                    }
                }
            }
        }
        __syncthreads();
    }

    // ---- epilogue: shfl-swap fragments into 4-col runs, scatter v4 reds ----
    // lane = g*4 + tig; pair lanes (tig even, tig odd) cover cols 4j..4j+3.
    // even lane keeps row g (c0,c1 + partner c0,c1); odd keeps row g+8.
    {
        const int g    = lane >> 2;
        const int tig  = lane & 3;
        const int oddp = tig & 1;
        #pragma unroll
        for (int mb = 0; mb < 2; mb++) {
            const int r    = wm * 32 + mb * 16 + g + oddp * 8;
            const int orow = mo[r];
            float* dst = acc_out + (size_t)orow * C + wn * 64 + (tig >> 1) * 4;
            #pragma unroll
            for (int nb = 0; nb < 8; nb++) {
                float s0 = oddp ? acc[mb][nb][0] : acc[mb][nb][2];
                float s1 = oddp ? acc[mb][nb][1] : acc[mb][nb][3];
                float r0 = __shfl_xor_sync(0xFFFFFFFFu, s0, 1);
                float r1 = __shfl_xor_sync(0xFFFFFFFFu, s1, 1);
                float v0 = oddp ? r0 : acc[mb][nb][0];
                float v1 = oddp ? r1 : acc[mb][nb][1];
                float v2 = oddp ? acc[mb][nb][2] : r0;
                float v3 = oddp ? acc[mb][nb][3] : r1;
                asm volatile("red.global.v4.f32.add [%0], {%1, %2, %3, %4};"
                             :: "l"(dst + nb * 8), "f"(v0), "f"(v1), "f"(v2), "f"(v3)
                             : "memory");
            }
        }
    }
}

// ---------------------------------------------------------------------------
// BN stats / finalize
// ---------------------------------------------------------------------------
__global__ void zero_stats_kernel()
{
    int c = threadIdx.x;
    g_sum[c] = 0.0f;
    g_sq[c]  = 0.0f;
}

__global__ __launch_bounds__(256)
void bn_stats_kernel(const float* __restrict__ a)
{
    __shared__ float4 ss[256];
    __shared__ float4 qq[256];
    const int tid = threadIdx.x;
    const int c4  = tid & 31;
    const int ro  = tid >> 5;

    float4 s = make_float4(0.f, 0.f, 0.f, 0.f);
    float4 p = make_float4(0.f, 0.f, 0.f, 0.f);
    for (int r = blockIdx.x * 8 + ro; r < N_PTS; r += gridDim.x * 8) {
        float4 v = ((const float4*)a)[(size_t)r * 32 + c4];
        s.x += v.x; s.y += v.y; s.z += v.z; s.w += v.w;
        p.x += v.x * v.x; p.y += v.y * v.y; p.z += v.z * v.z; p.w += v.w * v.w;
    }
    ss[tid] = s;
    qq[tid] = p;
    __syncthreads();
    if (tid < 32) {
        float4 S = ss[tid], Q = qq[tid];
        #pragma unroll
        for (int j = 1; j < 8; j++) {
            float4 s2 = ss[tid + j * 32], q2 = qq[tid + j * 32];
            S.x += s2.x; S.y += s2.y; S.z += s2.z; S.w += s2.w;
            Q.x += q2.x; Q.y += q2.y; Q.z += q2.z; Q.w += q2.w;
        }
        atomicAdd(&g_sum[tid * 4 + 0], S.x);
        atomicAdd(&g_sum[tid * 4 + 1], S.y);
        atomicAdd(&g_sum[tid * 4 + 2], S.z);
        atomicAdd(&g_sum[tid * 4 + 3], S.w);
        atomicAdd(&g_sq[tid * 4 + 0], Q.x);
        atomicAdd(&g_sq[tid * 4 + 1], Q.y);
        atomicAdd(&g_sq[tid * 4 + 2], Q.z);
        atomicAdd(&g_sq[tid * 4 + 3], Q.w);
    }
}

__global__ void bn_finalize_kernel(const float* __restrict__ gamma,
                                   const float* __restrict__ beta)
{
    int c = threadIdx.x;
    float m  = g_sum[c] * (1.0f / N_PTS);
    float v  = g_sq[c] * (1.0f / N_PTS) - m * m;
    float is = rsqrtf(v + EPS);
    float sc = is * gamma[c];
    g_scale[c] = sc;
    g_shift[c] = beta[c] - m * sc;
}

// ---------------------------------------------------------------------------
// Apply kernels
// ---------------------------------------------------------------------------
__device__ __forceinline__ float elu_f(float x)
{
    return x > 0.0f ? x : expm1f(x);
}

__global__ __launch_bounds__(256)
void apply_bn_elu_split_kernel(const float* __restrict__ a,
                               __nv_bfloat16* __restrict__ yh,
                               __nv_bfloat16* __restrict__ yl)
{
    size_t idx = (size_t)blockIdx.x * 256 + threadIdx.x;
    int c4 = (int)(idx & 31);
    float4 v  = ((const float4*)a)[idx];
    float4 sc = ((const float4*)g_scale)[c4];
    float4 sh = ((const float4*)g_shift)[c4];
    float4 r;
    r.x = elu_f(fmaf(v.x, sc.x, sh.x));
    r.y = elu_f(fmaf(v.y, sc.y, sh.y));
    r.z = elu_f(fmaf(v.z, sc.z, sh.z));
    r.w = elu_f(fmaf(v.w, sc.w, sh.w));
    __nv_bfloat16 h0, h1, h2, h3, l0, l1, l2, l3;
    split_bf16(r.x, h0, l0); split_bf16(r.y, h1, l1);
    split_bf16(r.z, h2, l2); split_bf16(r.w, h3, l3);
    ((__nv_bfloat162*)yh)[idx * 2 + 0] = __nv_bfloat162(h0, h1);
    ((__nv_bfloat162*)yh)[idx * 2 + 1] = __nv_bfloat162(h2, h3);
    ((__nv_bfloat162*)yl)[idx * 2 + 0] = __nv_bfloat162(l0, l1);
    ((__nv_bfloat162*)yl)[idx * 2 + 1] = __nv_bfloat162(l2, l3);
}

__global__ __launch_bounds__(256)
void apply_bn_res_elu_kernel(const float* __restrict__ a,
                             const float* __restrict__ resid,
                             float* __restrict__ o)
{
    size_t idx = (size_t)blockIdx.x * 256 + threadIdx.x;
    int c4 = (int)(idx & 31);
    float4 v  = ((const float4*)a)[idx];
    float4 rs = ((const float4*)resid)[idx];
    float4 sc = ((const float4*)g_scale)[c4];
    float4 sh = ((const float4*)g_shift)[c4];
    float4 r;
    r.x = elu_f(fmaf(v.x, sc.x, sh.x) + rs.x);
    r.y = elu_f(fmaf(v.y, sc.y, sh.y) + rs.y);
    r.z = elu_f(fmaf(v.z, sc.z, sh.z) + rs.z);
    r.w = elu_f(fmaf(v.w, sc.w, sh.w) + rs.w);
    ((float4*)o)[idx] = r;
}

// ---------------------------------------------------------------------------
// Launch
// ---------------------------------------------------------------------------
extern "C" void kernel_launch(void* const* d_in, const int* in_sizes, int n_in,
                              void* d_out, int out_size)
{
    const float* x       = (const float*)d_in[0];
    const float* W1      = (const float*)d_in[1];
    const float* gamma1  = (const float*)d_in[2];
    const float* beta1   = (const float*)d_in[3];
    const float* W2      = (const float*)d_in[4];
    const float* gamma2  = (const float*)d_in[5];
    const float* beta2   = (const float*)d_in[6];
    const int*   map1_in  = (const int*)d_in[7];
    const int*   map1_out = (const int*)d_in[8];
    const int*   map2_in  = (const int*)d_in[9];
    const int*   map2_out = (const int*)d_in[10];
    float* out = (float*)d_out;

    void *accPtr, *xhiPtr, *xloPtr, *yhiPtr, *yloPtr;
    cudaGetSymbolAddress(&accPtr, g_acc);
    cudaGetSymbolAddress(&xhiPtr, g_xhi);
    cudaGetSymbolAddress(&xloPtr, g_xlo);
    cudaGetSymbolAddress(&yhiPtr, g_yhi);
    cudaGetSymbolAddress(&yloPtr, g_ylo);
    const size_t accBytes = (size_t)N_PTS * C * sizeof(float);

    cudaFuncSetAttribute(spconv_mma_kernel,
                         cudaFuncAttributeMaxDynamicSharedMemorySize, DYN_SMEM);

    const dim3 convGrid(M_MAP / BT, KNUM);
    const int  elem4  = (N_PTS * C) / 4;
    const int  ewGrid = elem4 / 256;

    // ---- prepack ----
    prepack_x_kernel<<<ewGrid, 256>>>(x, (__nv_bfloat16*)xhiPtr, (__nv_bfloat16*)xloPtr);
    prepack_w_kernel<<<KNUM, 256>>>(W1);
    cudaMemsetAsync(accPtr, 0, accBytes);
    zero_stats_kernel<<<1, C>>>();

    // ---- layer 1 ----
    spconv_mma_kernel<<<convGrid, 256, DYN_SMEM>>>(
        (const __nv_bfloat16*)xhiPtr, (const __nv_bfloat16*)xloPtr,
        map1_in, map1_out, (float*)accPtr);
    bn_stats_kernel<<<512, 256>>>((const float*)accPtr);
    bn_finalize_kernel<<<1, C>>>(gamma1, beta1);
    apply_bn_elu_split_kernel<<<ewGrid, 256>>>(
        (const float*)accPtr, (__nv_bfloat16*)yhiPtr, (__nv_bfloat16*)yloPtr);

    // ---- layer 2 ----
    prepack_w_kernel<<<KNUM, 256>>>(W2);
    cudaMemsetAsync(accPtr, 0, accBytes);
    zero_stats_kernel<<<1, C>>>();
    spconv_mma_kernel<<<convGrid, 256, DYN_SMEM>>>(
        (const __nv_bfloat16*)yhiPtr, (const __nv_bfloat16*)yloPtr,
        map2_in, map2_out, (float*)accPtr);
    bn_stats_kernel<<<512, 256>>>((const float*)accPtr);
    bn_finalize_kernel<<<1, C>>>(gamma2, beta2);
    apply_bn_res_elu_kernel<<<ewGrid, 256>>>((const float*)accPtr, x, out);
}

// round 9
// speedup vs baseline: 2.6502x; 1.0821x over previous
#include <cuda_runtime.h>
#include <cuda_bf16.h>
#include <math.h>
#include <stdint.h>

#define N_PTS 131072
#define C 128
#define KNUM 27
#define M_MAP 65536
#define EPS 1e-5f

#define BT 128            // map rows per CTA tile
#define KC 32             // k-elems per chunk
#define NCHUNK (C / KC)   // 4
#define PB 80             // smem row pitch in BYTES (40 bf16) — LDSM conflict-free
#define ARR_SZ (BT * PB)  // 10240 B per operand array
#define STAGE_SZ (4 * ARR_SZ)   // Ahi, Alo, Bhi, Blo = 40960 B
#define DYN_SMEM (2 * STAGE_SZ) // 81920 B (2 stages)
#define WCHUNK_B ARR_SZ         // one weight chunk image = 10240 B

// ---- scratch (static device allocations; allowed) ----
__device__ __align__(16) float         g_acc[(size_t)N_PTS * C];
__device__ __align__(16) __nv_bfloat16 g_xhi[(size_t)N_PTS * C];
__device__ __align__(16) __nv_bfloat16 g_xlo[(size_t)N_PTS * C];
__device__ __align__(16) __nv_bfloat16 g_yhi[(size_t)N_PTS * C];
__device__ __align__(16) __nv_bfloat16 g_ylo[(size_t)N_PTS * C];
// weights pre-arranged as the exact smem tile image:
// [k][chunk][row 0..127][40 bf16 (80 B pitch, first 32 valid)]
__device__ __align__(16) __nv_bfloat16 g_wthi[(size_t)KNUM * NCHUNK * BT * (PB / 2)];
__device__ __align__(16) __nv_bfloat16 g_wtlo[(size_t)KNUM * NCHUNK * BT * (PB / 2)];
__device__ __align__(16) float g_sum[C];
__device__ __align__(16) float g_sq[C];
__device__ __align__(16) float g_scale[C];
__device__ __align__(16) float g_shift[C];

// ---------------------------------------------------------------------------
// helpers
// ---------------------------------------------------------------------------
__device__ __forceinline__ uint32_t smem_u32(const void* p)
{
    uint32_t a;
    asm("{ .reg .u64 t; cvta.to.shared.u64 t, %1; cvt.u32.u64 %0, t; }"
        : "=r"(a) : "l"(p));
    return a;
}

__device__ __forceinline__ void split_bf16(float v, __nv_bfloat16& h, __nv_bfloat16& l)
{
    h = __float2bfloat16_rn(v);
    l = __float2bfloat16_rn(v - __bfloat162float(h));
}

__device__ __forceinline__ void mma16816(float* c, const unsigned* a,
                                         unsigned b0, unsigned b1)
{
    asm volatile(
        "mma.sync.aligned.m16n8k16.row.col.f32.bf16.bf16.f32 "
        "{%0,%1,%2,%3}, {%4,%5,%6,%7}, {%8,%9}, {%0,%1,%2,%3};"
        : "+f"(c[0]), "+f"(c[1]), "+f"(c[2]), "+f"(c[3])
        : "r"(a[0]), "r"(a[1]), "r"(a[2]), "r"(a[3]), "r"(b0), "r"(b1));
}

__device__ __forceinline__ void ldsm_x4(unsigned* r, uint32_t addr)
{
    asm volatile("ldmatrix.sync.aligned.m8n8.x4.shared.b16 {%0,%1,%2,%3}, [%4];"
                 : "=r"(r[0]), "=r"(r[1]), "=r"(r[2]), "=r"(r[3]) : "r"(addr));
}

#define CP_ASYNC16(dst, src) \
    asm volatile("cp.async.cg.shared.global [%0], [%1], 16;" :: "r"(dst), "l"(src))
#define CP_COMMIT() asm volatile("cp.async.commit_group;" ::: "memory")

__device__ __forceinline__ void bulk_copy(uint32_t dst, const void* src,
                                          uint32_t bytes, uint32_t mbar)
{
    asm volatile(
        "cp.async.bulk.shared::cta.global.mbarrier::complete_tx::bytes "
        "[%0], [%1], %2, [%3];"
        :: "r"(dst), "l"(src), "r"(bytes), "r"(mbar) : "memory");
}

__device__ __forceinline__ void mbar_expect_tx(uint32_t mbar, uint32_t bytes)
{
    asm volatile("mbarrier.arrive.expect_tx.shared.b64 _, [%0], %1;"
                 :: "r"(mbar), "r"(bytes) : "memory");
}

__device__ __forceinline__ void mbar_wait(uint32_t mbar, uint32_t parity)
{
    uint32_t done;
    asm volatile(
        "{\n\t.reg .pred p;\n\t"
        "mbarrier.try_wait.parity.acquire.cta.shared::cta.b64 p, [%1], %2;\n\t"
        "selp.b32 %0, 1, 0, p;\n\t}"
        : "=r"(done) : "r"(mbar), "r"(parity) : "memory");
    if (!done) {
        asm volatile(
            "{\n\t.reg .pred P1;\n\t"
            "WL_%=:\n\t"
            "mbarrier.try_wait.parity.acquire.cta.shared::cta.b64 P1, [%0], %1, 0x989680;\n\t"
            "@P1 bra.uni WD_%=;\n\t"
            "bra.uni WL_%=;\n\t"
            "WD_%=:\n\t}"
            :: "r"(mbar), "r"(parity) : "memory");
    }
}

// ---------------------------------------------------------------------------
// Prepack kernels
// ---------------------------------------------------------------------------
__global__ __launch_bounds__(256)
void prepack_x_kernel(const float* __restrict__ src,
                      __nv_bfloat16* __restrict__ hi,
                      __nv_bfloat16* __restrict__ lo,
                      float* __restrict__ acc_zero)
{
    size_t i = (size_t)blockIdx.x * 256 + threadIdx.x;
    float4 v = ((const float4*)src)[i];
    __nv_bfloat16 h0, h1, h2, h3, l0, l1, l2, l3;
    split_bf16(v.x, h0, l0); split_bf16(v.y, h1, l1);
    split_bf16(v.z, h2, l2); split_bf16(v.w, h3, l3);
    ((__nv_bfloat162*)hi)[i * 2 + 0] = __nv_bfloat162(h0, h1);
    ((__nv_bfloat162*)hi)[i * 2 + 1] = __nv_bfloat162(h2, h3);
    ((__nv_bfloat162*)lo)[i * 2 + 0] = __nv_bfloat162(l0, l1);
    ((__nv_bfloat162*)lo)[i * 2 + 1] = __nv_bfloat162(l2, l3);
    ((float4*)acc_zero)[i] = make_float4(0.f, 0.f, 0.f, 0.f);   // layer-1 acc zero
}

// W[k][cin][n] fp32 -> smem-image layout: [k][chunk=cin>>5][n][cin&31] @ 80B pitch
__global__ __launch_bounds__(256)
void prepack_w_kernel(const float* __restrict__ W)
{
    int k = blockIdx.x;
    const float* Wk = W + (size_t)k * C * C;
    for (int idx = threadIdx.x; idx < C * C; idx += 256) {
        int n   = idx & (C - 1);
        int cin = idx >> 7;
        float v = Wk[(size_t)cin * C + n];
        __nv_bfloat16 h, l;
        split_bf16(v, h, l);
        int ch  = cin >> 5;
        int col = cin & 31;
        size_t off = ((size_t)(k * NCHUNK + ch) * BT + n) * (PB / 2) + col;
        g_wthi[off] = h;
        g_wtlo[off] = l;
    }
}

// ---------------------------------------------------------------------------
// Sparse conv: mma.sync + ldmatrix; A via cp.async, B via cp.async.bulk.
// CTA = 128 map rows x 128 out channels; 8 warps, warp tile 32M x 64N.
// ---------------------------------------------------------------------------
__global__ __launch_bounds__(256, 2)
void spconv_mma_kernel(const __nv_bfloat16* __restrict__ xhi,
                       const __nv_bfloat16* __restrict__ xlo,
                       const int* __restrict__ map_in,
                       const int* __restrict__ map_out,
                       float* __restrict__ acc_out)
{
    extern __shared__ __align__(16) char dynsmem[];
    __shared__ int rowidx[BT];
    __shared__ __align__(8) uint64_t s_mbar[2];

    const int k    = blockIdx.y;
    const int m0   = blockIdx.x * BT;
    const int tid  = threadIdx.x;
    const int warp = tid >> 5;
    const int lane = tid & 31;
    const int wm   = warp & 3;            // M warp: 32 rows
    const int wn   = warp >> 2;           // N warp: 64 cols

    const int* mi = map_in  + (size_t)k * M_MAP + m0;
    const int* mo = map_out + (size_t)k * M_MAP + m0;
    const char* wbh = (const char*)g_wthi + (size_t)k * NCHUNK * WCHUNK_B;
    const char* wbl = (const char*)g_wtlo + (size_t)k * NCHUNK * WCHUNK_B;

    const uint32_t sbase = smem_u32(dynsmem);
    const uint32_t mb0   = smem_u32(&s_mbar[0]);
    const uint32_t mb1   = smem_u32(&s_mbar[1]);

    if (tid < BT) rowidx[tid] = mi[tid];
    if (tid == 0) {
        asm volatile("mbarrier.init.shared.b64 [%0], 1;" :: "r"(mb0) : "memory");
        asm volatile("mbarrier.init.shared.b64 [%0], 1;" :: "r"(mb1) : "memory");
        asm volatile("fence.proxy.async.shared::cta;" ::: "memory");
    }
    __syncthreads();

    // --- per-thread cp.async source/dest for A (4 transfers per chunk) ---
    const __nv_bfloat16* srcs[4];
    uint32_t doffs[4];
    #pragma unroll
    for (int it = 0; it < 4; it++) {
        int idx = tid + it * 256;          // 0..1023
        int a   = idx >> 9;                // 0: hi, 1: lo
        int rem = idx & 511;
        int row = rem >> 2;
        int q   = rem & 3;
        const __nv_bfloat16* s = (a == 0 ? xhi : xlo) + (size_t)rowidx[row] * C;
        srcs[it]  = s + q * 8;
        doffs[it] = (uint32_t)(a * ARR_SZ + row * PB + q * 16);
    }

    // --- ldmatrix per-thread offsets (within a stage) ---
    const int mat = lane >> 3;
    const int mi8 = lane & 7;
    const uint32_t aRow  = (uint32_t)(wm * 32 + (mat & 1) * 8 + mi8);
    const uint32_t aColB = (uint32_t)((mat >> 1) * 8) * 2;
    uint32_t aOff[2];
    aOff[0] = aRow * PB + aColB;
    aOff[1] = (aRow + 16) * PB + aColB;
    const uint32_t bRow  = (uint32_t)(wn * 64 + (mat >> 1) * 8 + mi8);
    const uint32_t bColB = (uint32_t)((mat & 1) * 8) * 2;
    uint32_t bOff[4];
    #pragma unroll
    for (int p = 0; p < 4; p++)
        bOff[p] = 2 * ARR_SZ + (bRow + p * 16) * PB + bColB;

    float acc[2][8][4];
    #pragma unroll
    for (int i = 0; i < 2; i++)
        #pragma unroll
        for (int j = 0; j < 8; j++)
            #pragma unroll
            for (int t = 0; t < 4; t++) acc[i][j][t] = 0.0f;

    // ---- preload chunk 0 into stage 0 ----
    #pragma unroll
    for (int it = 0; it < 4; it++)
        CP_ASYNC16(sbase + doffs[it], srcs[it]);
    CP_COMMIT();
    if (tid == 0) {
        mbar_expect_tx(mb0, 2 * WCHUNK_B);
        bulk_copy(sbase + 2 * ARR_SZ, wbh, WCHUNK_B, mb0);
        bulk_copy(sbase + 3 * ARR_SZ, wbl, WCHUNK_B, mb0);
    }

    for (int ch = 0; ch < NCHUNK; ch++) {
        const uint32_t stage = (uint32_t)(ch & 1) * STAGE_SZ;
        if (ch + 1 < NCHUNK) {
            const uint32_t nstage = (uint32_t)((ch + 1) & 1) * STAGE_SZ;
            const int coff = (ch + 1) * KC;
            #pragma unroll
            for (int it = 0; it < 4; it++)
                CP_ASYNC16(sbase + nstage + doffs[it], srcs[it] + coff);
            CP_COMMIT();
            if (tid == 0) {
                const uint32_t nmb = ((ch + 1) & 1) ? mb1 : mb0;
                mbar_expect_tx(nmb, 2 * WCHUNK_B);
                bulk_copy(sbase + nstage + 2 * ARR_SZ,
                          wbh + (size_t)(ch + 1) * WCHUNK_B, WCHUNK_B, nmb);
                bulk_copy(sbase + nstage + 3 * ARR_SZ,
                          wbl + (size_t)(ch + 1) * WCHUNK_B, WCHUNK_B, nmb);
            }
            asm volatile("cp.async.wait_group 1;" ::: "memory");
        } else {
            asm volatile("cp.async.wait_group 0;" ::: "memory");
        }
        mbar_wait((ch & 1) ? mb1 : mb0, (uint32_t)((ch >> 1) & 1));
        __syncthreads();

        #pragma unroll
        for (int ks = 0; ks < KC / 16; ks++) {
            const uint32_t kb = (uint32_t)(ks * 32);
            unsigned ah[2][4], al[2][4];
            ldsm_x4(ah[0], sbase + stage + aOff[0] + kb);
            ldsm_x4(ah[1], sbase + stage + aOff[1] + kb);
            ldsm_x4(al[0], sbase + stage + ARR_SZ + aOff[0] + kb);
            ldsm_x4(al[1], sbase + stage + ARR_SZ + aOff[1] + kb);
            #pragma unroll
            for (int p = 0; p < 4; p++) {
                unsigned bh[4], bl[4];
                ldsm_x4(bh, sbase + stage + bOff[p] + kb);
                ldsm_x4(bl, sbase + stage + ARR_SZ + bOff[p] + kb);
                #pragma unroll
                for (int ns = 0; ns < 2; ns++) {
                    const int nb = p * 2 + ns;
                    #pragma unroll
                    for (int mb = 0; mb < 2; mb++) {
                        mma16816(acc[mb][nb], ah[mb], bh[ns * 2], bh[ns * 2 + 1]);
                        mma16816(acc[mb][nb], ah[mb], bl[ns * 2], bl[ns * 2 + 1]);
                        mma16816(acc[mb][nb], al[mb], bh[ns * 2], bh[ns * 2 + 1]);
                    }
                }
            }
        }
        __syncthreads();
    }

    // ---- epilogue: shfl-swap fragments into 4-col runs, scatter v4 reds ----
    {
        const int g    = lane >> 2;
        const int tig  = lane & 3;
        const int oddp = tig & 1;
        #pragma unroll
        for (int mb = 0; mb < 2; mb++) {
            const int r    = wm * 32 + mb * 16 + g + oddp * 8;
            const int orow = mo[r];
            float* dst = acc_out + (size_t)orow * C + wn * 64 + (tig >> 1) * 4;
            #pragma unroll
            for (int nb = 0; nb < 8; nb++) {
                float s0 = oddp ? acc[mb][nb][0] : acc[mb][nb][2];
                float s1 = oddp ? acc[mb][nb][1] : acc[mb][nb][3];
                float r0 = __shfl_xor_sync(0xFFFFFFFFu, s0, 1);
                float r1 = __shfl_xor_sync(0xFFFFFFFFu, s1, 1);
                float v0 = oddp ? r0 : acc[mb][nb][0];
                float v1 = oddp ? r1 : acc[mb][nb][1];
                float v2 = oddp ? acc[mb][nb][2] : r0;
                float v3 = oddp ? acc[mb][nb][3] : r1;
                asm volatile("red.global.v4.f32.add [%0], {%1, %2, %3, %4};"
                             :: "l"(dst + nb * 8), "f"(v0), "f"(v1), "f"(v2), "f"(v3)
                             : "memory");
            }
        }
    }
}

// ---------------------------------------------------------------------------
// BN stats / finalize
// ---------------------------------------------------------------------------
__global__ void zero_stats_kernel()
{
    int c = threadIdx.x;
    g_sum[c] = 0.0f;
    g_sq[c]  = 0.0f;
}

__global__ __launch_bounds__(256)
void bn_stats_kernel(const float* __restrict__ a)
{
    __shared__ float4 ss[256];
    __shared__ float4 qq[256];
    const int tid = threadIdx.x;
    const int c4  = tid & 31;
    const int ro  = tid >> 5;

    float4 s = make_float4(0.f, 0.f, 0.f, 0.f);
    float4 p = make_float4(0.f, 0.f, 0.f, 0.f);
    for (int r = blockIdx.x * 8 + ro; r < N_PTS; r += gridDim.x * 8) {
        float4 v = ((const float4*)a)[(size_t)r * 32 + c4];
        s.x += v.x; s.y += v.y; s.z += v.z; s.w += v.w;
        p.x += v.x * v.x; p.y += v.y * v.y; p.z += v.z * v.z; p.w += v.w * v.w;
    }
    ss[tid] = s;
    qq[tid] = p;
    __syncthreads();
    if (tid < 32) {
        float4 S = ss[tid], Q = qq[tid];
        #pragma unroll
        for (int j = 1; j < 8; j++) {
            float4 s2 = ss[tid + j * 32], q2 = qq[tid + j * 32];
            S.x += s2.x; S.y += s2.y; S.z += s2.z; S.w += s2.w;
            Q.x += q2.x; Q.y += q2.y; Q.z += q2.z; Q.w += q2.w;
        }
        atomicAdd(&g_sum[tid * 4 + 0], S.x);
        atomicAdd(&g_sum[tid * 4 + 1], S.y);
        atomicAdd(&g_sum[tid * 4 + 2], S.z);
        atomicAdd(&g_sum[tid * 4 + 3], S.w);
        atomicAdd(&g_sq[tid * 4 + 0], Q.x);
        atomicAdd(&g_sq[tid * 4 + 1], Q.y);
        atomicAdd(&g_sq[tid * 4 + 2], Q.z);
        atomicAdd(&g_sq[tid * 4 + 3], Q.w);
    }
}

__global__ void bn_finalize_kernel(const float* __restrict__ gamma,
                                   const float* __restrict__ beta)
{
    int c = threadIdx.x;
    float m  = g_sum[c] * (1.0f / N_PTS);
    float v  = g_sq[c] * (1.0f / N_PTS) - m * m;
    float is = rsqrtf(v + EPS);
    float sc = is * gamma[c];
    g_scale[c] = sc;
    g_shift[c] = beta[c] - m * sc;
}

// ---------------------------------------------------------------------------
// Apply kernels
// ---------------------------------------------------------------------------
__device__ __forceinline__ float elu_f(float x)
{
    return x > 0.0f ? x : expm1f(x);
}

// BN + ELU -> split bf16; also zeroes the accumulator for layer 2.
__global__ __launch_bounds__(256)
void apply_bn_elu_split_kernel(float* __restrict__ a,
                               __nv_bfloat16* __restrict__ yh,
                               __nv_bfloat16* __restrict__ yl)
{
    size_t idx = (size_t)blockIdx.x * 256 + threadIdx.x;
    int c4 = (int)(idx & 31);
    float4 v  = ((const float4*)a)[idx];
    float4 sc = ((const float4*)g_scale)[c4];
    float4 sh = ((const float4*)g_shift)[c4];
    ((float4*)a)[idx] = make_float4(0.f, 0.f, 0.f, 0.f);   // zero acc for layer 2
    float4 r;
    r.x = elu_f(fmaf(v.x, sc.x, sh.x));
    r.y = elu_f(fmaf(v.y, sc.y, sh.y));
    r.z = elu_f(fmaf(v.z, sc.z, sh.z));
    r.w = elu_f(fmaf(v.w, sc.w, sh.w));
    __nv_bfloat16 h0, h1, h2, h3, l0, l1, l2, l3;
    split_bf16(r.x, h0, l0); split_bf16(r.y, h1, l1);
    split_bf16(r.z, h2, l2); split_bf16(r.w, h3, l3);
    ((__nv_bfloat162*)yh)[idx * 2 + 0] = __nv_bfloat162(h0, h1);
    ((__nv_bfloat162*)yh)[idx * 2 + 1] = __nv_bfloat162(h2, h3);
    ((__nv_bfloat162*)yl)[idx * 2 + 0] = __nv_bfloat162(l0, l1);
    ((__nv_bfloat162*)yl)[idx * 2 + 1] = __nv_bfloat162(l2, l3);
}

__global__ __launch_bounds__(256)
void apply_bn_res_elu_kernel(const float* __restrict__ a,
                             const float* __restrict__ resid,
                             float* __restrict__ o)
{
    size_t idx = (size_t)blockIdx.x * 256 + threadIdx.x;
    int c4 = (int)(idx & 31);
    float4 v  = ((const float4*)a)[idx];
    float4 rs = ((const float4*)resid)[idx];
    float4 sc = ((const float4*)g_scale)[c4];
    float4 sh = ((const float4*)g_shift)[c4];
    float4 r;
    r.x = elu_f(fmaf(v.x, sc.x, sh.x) + rs.x);
    r.y = elu_f(fmaf(v.y, sc.y, sh.y) + rs.y);
    r.z = elu_f(fmaf(v.z, sc.z, sh.z) + rs.z);
    r.w = elu_f(fmaf(v.w, sc.w, sh.w) + rs.w);
    ((float4*)o)[idx] = r;
}

// ---------------------------------------------------------------------------
// Launch
// ---------------------------------------------------------------------------
extern "C" void kernel_launch(void* const* d_in, const int* in_sizes, int n_in,
                              void* d_out, int out_size)
{
    const float* x       = (const float*)d_in[0];
    const float* W1      = (const float*)d_in[1];
    const float* gamma1  = (const float*)d_in[2];
    const float* beta1   = (const float*)d_in[3];
    const float* W2      = (const float*)d_in[4];
    const float* gamma2  = (const float*)d_in[5];
    const float* beta2   = (const float*)d_in[6];
    const int*   map1_in  = (const int*)d_in[7];
    const int*   map1_out = (const int*)d_in[8];
    const int*   map2_in  = (const int*)d_in[9];
    const int*   map2_out = (const int*)d_in[10];
    float* out = (float*)d_out;

    void *accPtr, *xhiPtr, *xloPtr, *yhiPtr, *yloPtr;
    cudaGetSymbolAddress(&accPtr, g_acc);
    cudaGetSymbolAddress(&xhiPtr, g_xhi);
    cudaGetSymbolAddress(&xloPtr, g_xlo);
    cudaGetSymbolAddress(&yhiPtr, g_yhi);
    cudaGetSymbolAddress(&yloPtr, g_ylo);

    cudaFuncSetAttribute(spconv_mma_kernel,
                         cudaFuncAttributeMaxDynamicSharedMemorySize, DYN_SMEM);

    const dim3 convGrid(M_MAP / BT, KNUM);
    const int  elem4  = (N_PTS * C) / 4;
    const int  ewGrid = elem4 / 256;

    // ---- prepack (also zeroes layer-1 accumulator) ----
    prepack_x_kernel<<<ewGrid, 256>>>(x, (__nv_bfloat16*)xhiPtr,
                                      (__nv_bfloat16*)xloPtr, (float*)accPtr);
    prepack_w_kernel<<<KNUM, 256>>>(W1);
    zero_stats_kernel<<<1, C>>>();

    // ---- layer 1 ----
    spconv_mma_kernel<<<convGrid, 256, DYN_SMEM>>>(
        (const __nv_bfloat16*)xhiPtr, (const __nv_bfloat16*)xloPtr,
        map1_in, map1_out, (float*)accPtr);
    bn_stats_kernel<<<512, 256>>>((const float*)accPtr);
    bn_finalize_kernel<<<1, C>>>(gamma1, beta1);
    apply_bn_elu_split_kernel<<<ewGrid, 256>>>(
        (float*)accPtr, (__nv_bfloat16*)yhiPtr, (__nv_bfloat16*)yloPtr);

    // ---- layer 2 ----
    prepack_w_kernel<<<KNUM, 256>>>(W2);
    zero_stats_kernel<<<1, C>>>();
    spconv_mma_kernel<<<convGrid, 256, DYN_SMEM>>>(
        (const __nv_bfloat16*)yhiPtr, (const __nv_bfloat16*)yloPtr,
        map2_in, map2_out, (float*)accPtr);
    bn_stats_kernel<<<512, 256>>>((const float*)accPtr);
    bn_finalize_kernel<<<1, C>>>(gamma2, beta2);
    apply_bn_res_elu_kernel<<<ewGrid, 256>>>((const float*)accPtr, x, out);
}